// round 8
// baseline (speedup 1.0000x reference)
#include <cuda_runtime.h>
#include <cuda_bf16.h>
#include <cuda_fp16.h>
#include <cstdint>

// Problem constants
#define SEQL   2048
#define BATCH  2
#define NHEAD  16
#define DHEAD  64
#define DMODEL 1024
#define MTOK   (SEQL * BATCH)   // 4096 tokens
#define NBH    (BATCH * NHEAD)  // 32

// ---------------------------------------------------------------------------
// Scratch (device globals: allocation-free rule)
// ---------------------------------------------------------------------------
__device__ __nv_bfloat16 g_x_hi[(size_t)MTOK * DMODEL];
__device__ __nv_bfloat16 g_x_lo[(size_t)MTOK * DMODEL];
__device__ __nv_bfloat16 g_c_hi[(size_t)MTOK * DMODEL];
__device__ __nv_bfloat16 g_c_lo[(size_t)MTOK * DMODEL];
__device__ __nv_bfloat16 g_qw_hi[(size_t)DMODEL * DMODEL];
__device__ __nv_bfloat16 g_qw_lo[(size_t)DMODEL * DMODEL];
__device__ __nv_bfloat16 g_kw_hi[(size_t)DMODEL * DMODEL];
__device__ __nv_bfloat16 g_kw_lo[(size_t)DMODEL * DMODEL];
__device__ __nv_bfloat16 g_vw_hi[(size_t)DMODEL * DMODEL];
__device__ __nv_bfloat16 g_vw_lo[(size_t)DMODEL * DMODEL];
__device__ __nv_bfloat16 g_ow_hi[(size_t)DMODEL * DMODEL];
__device__ __nv_bfloat16 g_ow_lo[(size_t)DMODEL * DMODEL];
// attention operands (fp16)
__device__ __half g_qh[(size_t)NBH * SEQL * DHEAD];   // q hi
__device__ __half g_ql[(size_t)NBH * SEQL * DHEAD];   // q lo
__device__ __half g_kh[(size_t)NBH * SEQL * DHEAD];   // k single
__device__ __half g_vh[(size_t)NBH * SEQL * DHEAD];   // v single

// ---------------------------------------------------------------------------
// PTX helpers
// ---------------------------------------------------------------------------
__device__ __forceinline__ uint32_t smem_u32(const void* p) {
    uint32_t a;
    asm("{ .reg .u64 t; cvta.to.shared.u64 t, %1; cvt.u32.u64 %0, t; }"
        : "=r"(a) : "l"(p));
    return a;
}

__device__ __forceinline__ void cp16(uint32_t s, const void* g) {
    asm volatile("cp.async.cg.shared.global [%0], [%1], 16;" :: "r"(s), "l"(g));
}
__device__ __forceinline__ void cp_commit() {
    asm volatile("cp.async.commit_group;" ::: "memory");
}
template <int N>
__device__ __forceinline__ void cp_wait() {
    asm volatile("cp.async.wait_group %0;" :: "n"(N) : "memory");
}

__device__ __forceinline__ void ldm_x4(uint32_t* r, uint32_t addr) {
    asm volatile("ldmatrix.sync.aligned.m8n8.x4.shared.b16 {%0,%1,%2,%3}, [%4];"
                 : "=r"(r[0]), "=r"(r[1]), "=r"(r[2]), "=r"(r[3])
                 : "r"(addr));
}
__device__ __forceinline__ void ldm_x4_t(uint32_t* r, uint32_t addr) {
    asm volatile("ldmatrix.sync.aligned.m8n8.x4.trans.shared.b16 {%0,%1,%2,%3}, [%4];"
                 : "=r"(r[0]), "=r"(r[1]), "=r"(r[2]), "=r"(r[3])
                 : "r"(addr));
}
__device__ __forceinline__ void mma_bf16(float* d, const uint32_t* a,
                                         uint32_t b0, uint32_t b1) {
    asm volatile(
        "mma.sync.aligned.m16n8k16.row.col.f32.bf16.bf16.f32 "
        "{%0,%1,%2,%3}, {%4,%5,%6,%7}, {%8,%9}, {%0,%1,%2,%3};"
        : "+f"(d[0]), "+f"(d[1]), "+f"(d[2]), "+f"(d[3])
        : "r"(a[0]), "r"(a[1]), "r"(a[2]), "r"(a[3]), "r"(b0), "r"(b1));
}
__device__ __forceinline__ void mma_f16(float* d, const uint32_t* a,
                                        uint32_t b0, uint32_t b1) {
    asm volatile(
        "mma.sync.aligned.m16n8k16.row.col.f32.f16.f16.f32 "
        "{%0,%1,%2,%3}, {%4,%5,%6,%7}, {%8,%9}, {%0,%1,%2,%3};"
        : "+f"(d[0]), "+f"(d[1]), "+f"(d[2]), "+f"(d[3])
        : "r"(a[0]), "r"(a[1]), "r"(a[2]), "r"(a[3]), "r"(b0), "r"(b1));
}

__device__ __forceinline__ uint32_t pack2(float a, float b) {
    __nv_bfloat162 t = __floats2bfloat162_rn(a, b);
    return *reinterpret_cast<uint32_t*>(&t);
}
__device__ __forceinline__ void split2(float a, float b, uint32_t& hi, uint32_t& lo) {
    __nv_bfloat16 ha = __float2bfloat16(a);
    __nv_bfloat16 hb = __float2bfloat16(b);
    hi = pack2(__bfloat162float(ha), __bfloat162float(hb));
    lo = pack2(a - __bfloat162float(ha), b - __bfloat162float(hb));
}
__device__ __forceinline__ uint32_t pack2h(float a, float b) {
    __half2 t = __floats2half2_rn(a, b);
    return *reinterpret_cast<uint32_t*>(&t);
}
__device__ __forceinline__ void split2h(float a, float b, uint32_t& hi, uint32_t& lo) {
    __half ha = __float2half_rn(a);
    __half hb = __float2half_rn(b);
    __half2 t; t.x = ha; t.y = hb;
    hi = *reinterpret_cast<uint32_t*>(&t);
    lo = pack2h(a - __half2float(ha), b - __half2float(hb));
}

// ---------------------------------------------------------------------------
// fp32 -> (bf16 hi, bf16 lo)  — tokens
// ---------------------------------------------------------------------------
__global__ __launch_bounds__(256) void cvt_split(
    const float* __restrict__ x, __nv_bfloat16* __restrict__ hi,
    __nv_bfloat16* __restrict__ lo, int n)
{
    int i = (blockIdx.x * 256 + threadIdx.x) * 4;
    if (i >= n) return;
    float4 v = *reinterpret_cast<const float4*>(x + i);
    uint32_t h0, l0, h1, l1;
    split2(v.x, v.y, h0, l0);
    split2(v.z, v.w, h1, l1);
    uint32_t* ph = reinterpret_cast<uint32_t*>(hi + i);
    uint32_t* pl = reinterpret_cast<uint32_t*>(lo + i);
    ph[0] = h0; ph[1] = h1;
    pl[0] = l0; pl[1] = l1;
}

// Fused conversion of all 4 weight matrices: blockIdx.y selects matrix.
struct W4 {
    const float* src[4];
    __nv_bfloat16* hi[4];
    __nv_bfloat16* lo[4];
    float scale[4];
};
__global__ __launch_bounds__(256) void cvt_w4(W4 w, int n)
{
    int m = blockIdx.y;
    const float* x = w.src[m];
    __nv_bfloat16* hi = w.hi[m];
    __nv_bfloat16* lo = w.lo[m];
    float scale = w.scale[m];
    int i = (blockIdx.x * 256 + threadIdx.x) * 4;
    if (i >= n) return;
    float4 v = *reinterpret_cast<const float4*>(x + i);
    v.x *= scale; v.y *= scale; v.z *= scale; v.w *= scale;
    uint32_t h0, l0, h1, l1;
    split2(v.x, v.y, h0, l0);
    split2(v.z, v.w, h1, l1);
    uint32_t* ph = reinterpret_cast<uint32_t*>(hi + i);
    uint32_t* pl = reinterpret_cast<uint32_t*>(lo + i);
    ph[0] = h0; ph[1] = h1;
    pl[0] = l0; pl[1] = l1;
}

// ---------------------------------------------------------------------------
// GEMM core: 128x128 CTA tile, BK=32, 8 warps, cp.async 2-stage pipeline.
// bf16 hi/lo compensated (3 passes), fp32 accumulate.
// ---------------------------------------------------------------------------
#define AST    40
#define G_ARR  10240
#define G_STG  (4 * G_ARR)
#define G_SMEM (2 * G_STG)   // 81920

__device__ __forceinline__ void gemm_issue(
    uint32_t sbase, int st,
    const __nv_bfloat16* Ahi, const __nv_bfloat16* Alo,
    const __nv_bfloat16* Bhi, const __nv_bfloat16* Blo,
    int m0, int n0, int kc, int K, int tid)
{
    uint32_t b = sbase + st * G_STG;
#pragma unroll
    for (int i = 0; i < 2; i++) {
        int chunk = tid + i * 256;
        int row = chunk >> 2;
        int c8 = (chunk & 3) * 8;
        uint32_t so = (uint32_t)(row * AST + c8) * 2;
        size_t offA = (size_t)(m0 + row) * K + kc + c8;
        size_t offB = (size_t)(n0 + row) * K + kc + c8;
        cp16(b + so,              Ahi + offA);
        cp16(b + G_ARR + so,      Alo + offA);
        cp16(b + 2 * G_ARR + so,  Bhi + offB);
        cp16(b + 3 * G_ARR + so,  Blo + offB);
    }
}

__device__ __forceinline__ void gemm_core(
    uint32_t sbase,
    const __nv_bfloat16* Ahi, const __nv_bfloat16* Alo,
    const __nv_bfloat16* Bhi, const __nv_bfloat16* Blo,
    int m0, int n0, int K, int tid, float acc[4][4][4])
{
    const int wid = tid >> 5;
    const int lid = tid & 31;
    const int wr = wid >> 2;
    const int wc = wid & 3;
    const int aRow = lid & 15;
    const int aCol = (lid >> 4) << 3;
    const int bRow = (lid & 7) + ((lid & 16) >> 1);
    const int bCol = ((lid >> 3) & 1) << 3;

    const int nIter = K >> 5;
    gemm_issue(sbase, 0, Ahi, Alo, Bhi, Blo, m0, n0, 0, K, tid);
    cp_commit();

    for (int it = 0; it < nIter; it++) {
        if (it + 1 < nIter) {
            gemm_issue(sbase, (it + 1) & 1, Ahi, Alo, Bhi, Blo,
                       m0, n0, (it + 1) << 5, K, tid);
            cp_commit();
            cp_wait<1>();
        } else {
            cp_wait<0>();
        }
        __syncthreads();

        const uint32_t bA_h = sbase + (it & 1) * G_STG;
        const uint32_t bA_l = bA_h + G_ARR;
        const uint32_t bB_h = bA_h + 2 * G_ARR;
        const uint32_t bB_l = bA_h + 3 * G_ARR;

#pragma unroll
        for (int ks = 0; ks < 32; ks += 16) {
            uint32_t ah[4][4], al[4][4];
#pragma unroll
            for (int mi = 0; mi < 4; mi++) {
                uint32_t off = (uint32_t)((wr * 64 + mi * 16 + aRow) * AST + ks + aCol) * 2;
                ldm_x4(ah[mi], bA_h + off);
                ldm_x4(al[mi], bA_l + off);
            }
            uint32_t bh[2][4], bl[2][4];
#pragma unroll
            for (int p = 0; p < 2; p++) {
                uint32_t off = (uint32_t)((wc * 32 + p * 16 + bRow) * AST + ks + bCol) * 2;
                ldm_x4(bh[p], bB_h + off);
                ldm_x4(bl[p], bB_l + off);
            }
#pragma unroll
            for (int mi = 0; mi < 4; mi++)
#pragma unroll
                for (int p = 0; p < 2; p++)
#pragma unroll
                    for (int s = 0; s < 2; s++) {
                        float* d = acc[mi][p * 2 + s];
                        mma_bf16(d, ah[mi], bh[p][s * 2], bh[p][s * 2 + 1]);
                        mma_bf16(d, ah[mi], bl[p][s * 2], bl[p][s * 2 + 1]);
                        mma_bf16(d, al[mi], bh[p][s * 2], bh[p][s * 2 + 1]);
                    }
        }
        __syncthreads();
    }
}

// Fused Q/K/V projection: grid (N/128, M/128, 3). Epilogue per z:
//   z=0: q -> fp16 hi/lo (bias*qscale)
//   z=1: k -> fp16 single
//   z=2: v -> fp16 single
struct ProjSet {
    const __nv_bfloat16 *Bh, *Bl;
    const float* bias;
    float bscale;
    __half *Ch, *Cl;   // Cl unused for k/v
};

__global__ __launch_bounds__(256, 1)
void gemm_qkv(const __nv_bfloat16* __restrict__ Ahi, const __nv_bfloat16* __restrict__ Alo,
              ProjSet p0, ProjSet p1, ProjSet p2, int M, int N, int K)
{
    extern __shared__ char smem[];
    const uint32_t sbase = smem_u32(smem);
    const int tid = threadIdx.x;
    const int z = blockIdx.z;
    const ProjSet P = (z == 0) ? p0 : (z == 1) ? p1 : p2;

    const int m0 = blockIdx.y * 128;
    const int n0 = blockIdx.x * 128;

    float acc[4][4][4];
#pragma unroll
    for (int i = 0; i < 4; i++)
#pragma unroll
        for (int j = 0; j < 4; j++)
#pragma unroll
            for (int e = 0; e < 4; e++) acc[i][j][e] = 0.f;

    gemm_core(sbase, Ahi, Alo, P.Bh, P.Bl, m0, n0, K, tid, acc);

    const int wid = tid >> 5;
    const int lid = tid & 31;
    const int wr = wid >> 2;
    const int wc = wid & 3;
    const int tq = lid >> 2;
    const int tr = (lid & 3) * 2;
#pragma unroll
    for (int mi = 0; mi < 4; mi++) {
#pragma unroll
        for (int ni = 0; ni < 4; ni++) {
            int gm = m0 + wr * 64 + mi * 16 + tq;
            int gn = n0 + wc * 32 + ni * 8 + tr;
            float2 bb = *reinterpret_cast<const float2*>(P.bias + gn);
#pragma unroll
            for (int half = 0; half < 2; half++) {
                int row = gm + half * 8;
                float ox = acc[mi][ni][half * 2 + 0] + bb.x * P.bscale;
                float oy = acc[mi][ni][half * 2 + 1] + bb.y * P.bscale;
                int s = row >> 1;
                int b = row & 1;
                int h = gn >> 6;
                int dh = gn & 63;
                size_t di = (((size_t)(b * NHEAD + h) * SEQL + s) * DHEAD + dh);
                if (z == 0) {
                    uint32_t hi, lo;
                    split2h(ox, oy, hi, lo);
                    *reinterpret_cast<uint32_t*>(P.Ch + di) = hi;
                    *reinterpret_cast<uint32_t*>(P.Cl + di) = lo;
                } else {
                    *reinterpret_cast<uint32_t*>(P.Ch + di) = pack2h(ox, oy);
                }
            }
        }
    }
}

// Output projection: fp32 row-major C
__global__ __launch_bounds__(256, 1)
void gemm_out(const __nv_bfloat16* __restrict__ Ahi, const __nv_bfloat16* __restrict__ Alo,
              const __nv_bfloat16* __restrict__ Bhi, const __nv_bfloat16* __restrict__ Blo,
              const float* __restrict__ bias, float* __restrict__ C,
              int M, int N, int K)
{
    extern __shared__ char smem[];
    const uint32_t sbase = smem_u32(smem);
    const int tid = threadIdx.x;

    const int m0 = blockIdx.y * 128;
    const int n0 = blockIdx.x * 128;

    float acc[4][4][4];
#pragma unroll
    for (int i = 0; i < 4; i++)
#pragma unroll
        for (int j = 0; j < 4; j++)
#pragma unroll
            for (int e = 0; e < 4; e++) acc[i][j][e] = 0.f;

    gemm_core(sbase, Ahi, Alo, Bhi, Blo, m0, n0, K, tid, acc);

    const int wid = tid >> 5;
    const int lid = tid & 31;
    const int wr = wid >> 2;
    const int wc = wid & 3;
    const int tq = lid >> 2;
    const int tr = (lid & 3) * 2;
#pragma unroll
    for (int mi = 0; mi < 4; mi++) {
#pragma unroll
        for (int ni = 0; ni < 4; ni++) {
            int gm = m0 + wr * 64 + mi * 16 + tq;
            int gn = n0 + wc * 32 + ni * 8 + tr;
            float2 bb = *reinterpret_cast<const float2*>(bias + gn);
#pragma unroll
            for (int half = 0; half < 2; half++) {
                int row = gm + half * 8;
                float2 o;
                o.x = acc[mi][ni][half * 2 + 0] + bb.x;
                o.y = acc[mi][ni][half * 2 + 1] + bb.y;
                *reinterpret_cast<float2*>(C + (size_t)row * N + gn) = o;
            }
        }
    }
}

// ---------------------------------------------------------------------------
// fp16 tensor-core causal flash attention, cp.async 2-stage K/V pipeline.
// Block: 128 threads (4 warps), 64 queries of one (b,h). Key tile 64.
// S = Qh*K + Ql*K (2 passes); O += P16 * V16 (1 pass).
// ---------------------------------------------------------------------------
#define KST    72
#define A_ARR  9216                    // 64*KST*2 bytes per array
#define A_STG  (2 * A_ARR)             // K + V per stage
#define A_SMEM (2 * A_STG)             // 36864

__device__ __forceinline__ void attn_issue(
    uint32_t sbase, int st,
    const __half* kh, const __half* vh, size_t koff, int tid)
{
    uint32_t b = sbase + st * A_STG;
#pragma unroll
    for (int i = tid; i < 512; i += 128) {
        int row = i >> 3, c8 = (i & 7) * 8;
        uint32_t so = (uint32_t)(row * KST + c8) * 2;
        size_t go = koff + row * 64 + c8;
        cp16(b + so,         kh + go);
        cp16(b + A_ARR + so, vh + go);
    }
}

__global__ __launch_bounds__(128, 3) void attn_mma(
    const __half* __restrict__ qh, const __half* __restrict__ ql,
    const __half* __restrict__ kh, const __half* __restrict__ vh,
    __nv_bfloat16* __restrict__ ch, __nv_bfloat16* __restrict__ cl)
{
    extern __shared__ char smem[];
    const uint32_t sbase = smem_u32(smem);

    const int qt  = (int)(gridDim.x - 1) - (int)blockIdx.x;  // long blocks first
    const int bh  = blockIdx.y;
    const int tid = threadIdx.x;
    const int wq  = tid >> 5;
    const int lid = tid & 31;

    const size_t headoff = (size_t)bh * SEQL * DHEAD;

    // ---- stage Q hi/lo tiles into stage-0 slots, load persistent fragments
    {
        const __half* Qh = qh + headoff + (size_t)qt * 64 * DHEAD;
        const __half* Ql = ql + headoff + (size_t)qt * 64 * DHEAD;
#pragma unroll
        for (int i = tid; i < 512; i += 128) {
            int row = i >> 3, c8 = (i & 7) * 8;
            uint32_t so = (uint32_t)(row * KST + c8) * 2;
            *reinterpret_cast<uint4*>(smem + so) =
                *reinterpret_cast<const uint4*>(Qh + row * 64 + c8);
            *reinterpret_cast<uint4*>(smem + A_ARR + so) =
                *reinterpret_cast<const uint4*>(Ql + row * 64 + c8);
        }
    }
    __syncthreads();

    const int aRow = lid & 15;
    const int aCol = (lid >> 4) << 3;
    uint32_t qfh[4][4], qfl[4][4];
#pragma unroll
    for (int ks = 0; ks < 4; ks++) {
        uint32_t off = (uint32_t)((wq * 16 + aRow) * KST + ks * 16 + aCol) * 2;
        ldm_x4(qfh[ks], sbase + off);
        ldm_x4(qfl[ks], sbase + A_ARR + off);
    }
    __syncthreads();   // Q fragments read before stage-0 is overwritten

    attn_issue(sbase, 0, kh, vh, headoff, tid);
    cp_commit();

    float O[8][4];
#pragma unroll
    for (int i = 0; i < 8; i++)
#pragma unroll
        for (int e = 0; e < 4; e++) O[i][e] = 0.f;
    float m0 = -1e30f, m1 = -1e30f, l0 = 0.f, l1 = 0.f;

    const int bRow = (lid & 7) + ((lid & 16) >> 1);
    const int bCol = ((lid >> 3) & 1) << 3;
    const int r0 = wq * 16 + (lid >> 2);

    for (int kt = 0; kt <= qt; kt++) {
        if (kt < qt) {
            attn_issue(sbase, (kt + 1) & 1, kh, vh,
                       headoff + (size_t)(kt + 1) * 64 * DHEAD, tid);
            cp_commit();
            cp_wait<1>();
        } else {
            cp_wait<0>();
        }
        __syncthreads();

        const uint32_t bK = sbase + (kt & 1) * A_STG;
        const uint32_t bV = bK + A_ARR;

        // ---- S = Qh K + Ql K (2 passes)
        float S[8][4];
#pragma unroll
        for (int i = 0; i < 8; i++)
#pragma unroll
            for (int e = 0; e < 4; e++) S[i][e] = 0.f;
#pragma unroll
        for (int ks = 0; ks < 4; ks++) {
#pragma unroll
            for (int ng = 0; ng < 4; ng++) {
                uint32_t kf[4];
                uint32_t off = (uint32_t)((ng * 16 + bRow) * KST + ks * 16 + bCol) * 2;
                ldm_x4(kf, bK + off);
#pragma unroll
                for (int s = 0; s < 2; s++) {
                    float* d = S[ng * 2 + s];
                    mma_f16(d, qfh[ks], kf[s * 2], kf[s * 2 + 1]);
                    mma_f16(d, qfl[ks], kf[s * 2], kf[s * 2 + 1]);
                }
            }
        }

        // ---- causal mask (diagonal tile)
        if (kt == qt) {
#pragma unroll
            for (int ni = 0; ni < 8; ni++) {
                int c = ni * 8 + (lid & 3) * 2;
                if (c > r0)         S[ni][0] = -1e30f;
                if (c + 1 > r0)     S[ni][1] = -1e30f;
                if (c > r0 + 8)     S[ni][2] = -1e30f;
                if (c + 1 > r0 + 8) S[ni][3] = -1e30f;
            }
        }

        // ---- online softmax
        float mx0 = -1e30f, mx1 = -1e30f;
#pragma unroll
        for (int ni = 0; ni < 8; ni++) {
            mx0 = fmaxf(mx0, fmaxf(S[ni][0], S[ni][1]));
            mx1 = fmaxf(mx1, fmaxf(S[ni][2], S[ni][3]));
        }
        mx0 = fmaxf(mx0, __shfl_xor_sync(0xffffffffu, mx0, 1));
        mx0 = fmaxf(mx0, __shfl_xor_sync(0xffffffffu, mx0, 2));
        mx1 = fmaxf(mx1, __shfl_xor_sync(0xffffffffu, mx1, 1));
        mx1 = fmaxf(mx1, __shfl_xor_sync(0xffffffffu, mx1, 2));
        float mn0 = fmaxf(m0, mx0), mn1 = fmaxf(m1, mx1);
        float c0 = __expf(m0 - mn0), c1 = __expf(m1 - mn1);
        m0 = mn0; m1 = mn1;

        uint32_t pA[8], pB[8];
        float s0 = 0.f, s1 = 0.f;
#pragma unroll
        for (int ni = 0; ni < 8; ni++) {
            float p0 = __expf(S[ni][0] - m0);
            float p1 = __expf(S[ni][1] - m0);
            float p2 = __expf(S[ni][2] - m1);
            float p3 = __expf(S[ni][3] - m1);
            s0 += p0 + p1;
            s1 += p2 + p3;
            pA[ni] = pack2h(p0, p1);
            pB[ni] = pack2h(p2, p3);
        }
        s0 += __shfl_xor_sync(0xffffffffu, s0, 1);
        s0 += __shfl_xor_sync(0xffffffffu, s0, 2);
        s1 += __shfl_xor_sync(0xffffffffu, s1, 1);
        s1 += __shfl_xor_sync(0xffffffffu, s1, 2);
        l0 = l0 * c0 + s0;
        l1 = l1 * c1 + s1;
#pragma unroll
        for (int ni = 0; ni < 8; ni++) {
            O[ni][0] *= c0; O[ni][1] *= c0;
            O[ni][2] *= c1; O[ni][3] *= c1;
        }

        // ---- O += P V (1 pass, fp16)
#pragma unroll
        for (int ks = 0; ks < 4; ks++) {
            uint32_t aP[4] = {pA[2 * ks], pB[2 * ks], pA[2 * ks + 1], pB[2 * ks + 1]};
#pragma unroll
            for (int ng = 0; ng < 4; ng++) {
                uint32_t vf[4];
                uint32_t off = (uint32_t)((ks * 16 + (lid & 15)) * KST + ng * 16 + ((lid >> 4) << 3)) * 2;
                ldm_x4_t(vf, bV + off);
#pragma unroll
                for (int s = 0; s < 2; s++)
                    mma_f16(O[ng * 2 + s], aP, vf[s * 2], vf[s * 2 + 1]);
            }
        }
        __syncthreads();
    }

    // ---- epilogue: normalize, split to bf16 hi/lo, scatter to ctx [t][d]
    const float inv0 = 1.f / l0;
    const float inv1 = 1.f / l1;
    const int b = bh >> 4;
    const int h = bh & 15;
    const int sq = qt * 64 + wq * 16 + (lid >> 2);
#pragma unroll
    for (int ni = 0; ni < 8; ni++) {
        int col = h * 64 + ni * 8 + (lid & 3) * 2;
        uint32_t hi, lo;
        split2(O[ni][0] * inv0, O[ni][1] * inv0, hi, lo);
        size_t d0 = (size_t)(sq * BATCH + b) * DMODEL + col;
        *reinterpret_cast<uint32_t*>(ch + d0) = hi;
        *reinterpret_cast<uint32_t*>(cl + d0) = lo;
        split2(O[ni][2] * inv1, O[ni][3] * inv1, hi, lo);
        size_t d1 = (size_t)((sq + 8) * BATCH + b) * DMODEL + col;
        *reinterpret_cast<uint32_t*>(ch + d1) = hi;
        *reinterpret_cast<uint32_t*>(cl + d1) = lo;
    }
}

// ---------------------------------------------------------------------------
// Launch
// ---------------------------------------------------------------------------
extern "C" void kernel_launch(void* const* d_in, const int* in_sizes, int n_in,
                              void* d_out, int out_size)
{
    const float* query = (const float*)d_in[0];
    const float* q_w   = (const float*)d_in[1];
    const float* q_b   = (const float*)d_in[2];
    const float* k_w   = (const float*)d_in[3];
    const float* k_b   = (const float*)d_in[4];
    const float* v_w   = (const float*)d_in[5];
    const float* v_b   = (const float*)d_in[6];
    const float* out_w = (const float*)d_in[7];
    const float* out_b = (const float*)d_in[8];
    float* out = (float*)d_out;

    __nv_bfloat16 *xh, *xl, *ch, *cl;
    __nv_bfloat16 *qwh, *qwl, *kwh, *kwl, *vwh, *vwl, *owh, *owl;
    __half *qhp, *qlp, *khp, *vhp;
    cudaGetSymbolAddress((void**)&xh, g_x_hi);
    cudaGetSymbolAddress((void**)&xl, g_x_lo);
    cudaGetSymbolAddress((void**)&ch, g_c_hi);
    cudaGetSymbolAddress((void**)&cl, g_c_lo);
    cudaGetSymbolAddress((void**)&qwh, g_qw_hi);
    cudaGetSymbolAddress((void**)&qwl, g_qw_lo);
    cudaGetSymbolAddress((void**)&kwh, g_kw_hi);
    cudaGetSymbolAddress((void**)&kwl, g_kw_lo);
    cudaGetSymbolAddress((void**)&vwh, g_vw_hi);
    cudaGetSymbolAddress((void**)&vwl, g_vw_lo);
    cudaGetSymbolAddress((void**)&owh, g_ow_hi);
    cudaGetSymbolAddress((void**)&owl, g_ow_lo);
    cudaGetSymbolAddress((void**)&qhp, g_qh);
    cudaGetSymbolAddress((void**)&qlp, g_ql);
    cudaGetSymbolAddress((void**)&khp, g_kh);
    cudaGetSymbolAddress((void**)&vhp, g_vh);

    static bool attr_done = false;
    if (!attr_done) {
        cudaFuncSetAttribute(gemm_qkv, cudaFuncAttributeMaxDynamicSharedMemorySize, G_SMEM);
        cudaFuncSetAttribute(gemm_out, cudaFuncAttributeMaxDynamicSharedMemorySize, G_SMEM);
        cudaFuncSetAttribute(attn_mma, cudaFuncAttributeMaxDynamicSharedMemorySize, A_SMEM);
        attr_done = true;
    }

    const int nTok = MTOK * DMODEL;      // 4M
    const int nW   = DMODEL * DMODEL;    // 1M
    const float qscale = 0.125f;

    cvt_split<<<nTok / 1024, 256>>>(query, xh, xl, nTok);

    W4 w4;
    w4.src[0] = q_w;  w4.hi[0] = qwh; w4.lo[0] = qwl; w4.scale[0] = qscale;
    w4.src[1] = k_w;  w4.hi[1] = kwh; w4.lo[1] = kwl; w4.scale[1] = 1.0f;
    w4.src[2] = v_w;  w4.hi[2] = vwh; w4.lo[2] = vwl; w4.scale[2] = 1.0f;
    w4.src[3] = out_w; w4.hi[3] = owh; w4.lo[3] = owl; w4.scale[3] = 1.0f;
    dim3 gw(nW / 1024, 4);
    cvt_w4<<<gw, 256>>>(w4, nW);

    ProjSet pq = {qwh, qwl, q_b, qscale, qhp, qlp};
    ProjSet pk = {kwh, kwl, k_b, 1.0f,   khp, nullptr};
    ProjSet pv = {vwh, vwl, v_b, 1.0f,   vhp, nullptr};

    dim3 gqkv(DMODEL / 128, MTOK / 128, 3);   // (8, 32, 3)
    gemm_qkv<<<gqkv, 256, G_SMEM>>>(xh, xl, pq, pk, pv, MTOK, DMODEL, DMODEL);

    dim3 gattn(SEQL / 64, NBH);               // (32, 32)
    attn_mma<<<gattn, 128, A_SMEM>>>(qhp, qlp, khp, vhp, ch, cl);

    dim3 gout(DMODEL / 128, MTOK / 128);      // (8, 32)
    gemm_out<<<gout, 256, G_SMEM>>>(ch, cl, owh, owl, out_b, out, MTOK, DMODEL, DMODEL);
}

// round 9
// speedup vs baseline: 1.1858x; 1.1858x over previous
#include <cuda_runtime.h>
#include <cuda_bf16.h>
#include <cuda_fp16.h>
#include <cstdint>

// Problem constants
#define SEQL   2048
#define BATCH  2
#define NHEAD  16
#define DHEAD  64
#define DMODEL 1024
#define MTOK   (SEQL * BATCH)   // 4096 tokens
#define NBH    (BATCH * NHEAD)  // 32

// ---------------------------------------------------------------------------
// Scratch (device globals)
// ---------------------------------------------------------------------------
// fp16 path (QKV projections + attention)
__device__ __half g_x16h[(size_t)MTOK * DMODEL];
__device__ __half g_x16l[(size_t)MTOK * DMODEL];
__device__ __half g_qw16[(size_t)DMODEL * DMODEL];
__device__ __half g_kw16[(size_t)DMODEL * DMODEL];
__device__ __half g_vw16[(size_t)DMODEL * DMODEL];
__device__ __half g_qh[(size_t)NBH * SEQL * DHEAD];
__device__ __half g_ql[(size_t)NBH * SEQL * DHEAD];
__device__ __half g_kh[(size_t)NBH * SEQL * DHEAD];
__device__ __half g_vh[(size_t)NBH * SEQL * DHEAD];
// bf16 path (out projection)
__device__ __nv_bfloat16 g_c_hi[(size_t)MTOK * DMODEL];
__device__ __nv_bfloat16 g_c_lo[(size_t)MTOK * DMODEL];
__device__ __nv_bfloat16 g_ow_hi[(size_t)DMODEL * DMODEL];
__device__ __nv_bfloat16 g_ow_lo[(size_t)DMODEL * DMODEL];

// ---------------------------------------------------------------------------
// PTX helpers
// ---------------------------------------------------------------------------
__device__ __forceinline__ uint32_t smem_u32(const void* p) {
    uint32_t a;
    asm("{ .reg .u64 t; cvta.to.shared.u64 t, %1; cvt.u32.u64 %0, t; }"
        : "=r"(a) : "l"(p));
    return a;
}

__device__ __forceinline__ void cp16(uint32_t s, const void* g) {
    asm volatile("cp.async.cg.shared.global [%0], [%1], 16;" :: "r"(s), "l"(g));
}
__device__ __forceinline__ void cp_commit() {
    asm volatile("cp.async.commit_group;" ::: "memory");
}
template <int N>
__device__ __forceinline__ void cp_wait() {
    asm volatile("cp.async.wait_group %0;" :: "n"(N) : "memory");
}

__device__ __forceinline__ void ldm_x4(uint32_t* r, uint32_t addr) {
    asm volatile("ldmatrix.sync.aligned.m8n8.x4.shared.b16 {%0,%1,%2,%3}, [%4];"
                 : "=r"(r[0]), "=r"(r[1]), "=r"(r[2]), "=r"(r[3])
                 : "r"(addr));
}
__device__ __forceinline__ void ldm_x4_t(uint32_t* r, uint32_t addr) {
    asm volatile("ldmatrix.sync.aligned.m8n8.x4.trans.shared.b16 {%0,%1,%2,%3}, [%4];"
                 : "=r"(r[0]), "=r"(r[1]), "=r"(r[2]), "=r"(r[3])
                 : "r"(addr));
}
__device__ __forceinline__ void mma_bf16(float* d, const uint32_t* a,
                                         uint32_t b0, uint32_t b1) {
    asm volatile(
        "mma.sync.aligned.m16n8k16.row.col.f32.bf16.bf16.f32 "
        "{%0,%1,%2,%3}, {%4,%5,%6,%7}, {%8,%9}, {%0,%1,%2,%3};"
        : "+f"(d[0]), "+f"(d[1]), "+f"(d[2]), "+f"(d[3])
        : "r"(a[0]), "r"(a[1]), "r"(a[2]), "r"(a[3]), "r"(b0), "r"(b1));
}
__device__ __forceinline__ void mma_f16(float* d, const uint32_t* a,
                                        uint32_t b0, uint32_t b1) {
    asm volatile(
        "mma.sync.aligned.m16n8k16.row.col.f32.f16.f16.f32 "
        "{%0,%1,%2,%3}, {%4,%5,%6,%7}, {%8,%9}, {%0,%1,%2,%3};"
        : "+f"(d[0]), "+f"(d[1]), "+f"(d[2]), "+f"(d[3])
        : "r"(a[0]), "r"(a[1]), "r"(a[2]), "r"(a[3]), "r"(b0), "r"(b1));
}

__device__ __forceinline__ uint32_t pack2(float a, float b) {
    __nv_bfloat162 t = __floats2bfloat162_rn(a, b);
    return *reinterpret_cast<uint32_t*>(&t);
}
__device__ __forceinline__ void split2(float a, float b, uint32_t& hi, uint32_t& lo) {
    __nv_bfloat16 ha = __float2bfloat16(a);
    __nv_bfloat16 hb = __float2bfloat16(b);
    hi = pack2(__bfloat162float(ha), __bfloat162float(hb));
    lo = pack2(a - __bfloat162float(ha), b - __bfloat162float(hb));
}
__device__ __forceinline__ uint32_t pack2h(float a, float b) {
    __half2 t = __floats2half2_rn(a, b);
    return *reinterpret_cast<uint32_t*>(&t);
}
__device__ __forceinline__ void split2h(float a, float b, uint32_t& hi, uint32_t& lo) {
    __half ha = __float2half_rn(a);
    __half hb = __float2half_rn(b);
    __half2 t; t.x = ha; t.y = hb;
    hi = *reinterpret_cast<uint32_t*>(&t);
    lo = pack2h(a - __half2float(ha), b - __half2float(hb));
}

// ---------------------------------------------------------------------------
// Conversions
// ---------------------------------------------------------------------------
__global__ __launch_bounds__(256) void cvt_x16(
    const float* __restrict__ x, __half* __restrict__ hi,
    __half* __restrict__ lo, int n)
{
    int i = (blockIdx.x * 256 + threadIdx.x) * 4;
    if (i >= n) return;
    float4 v = *reinterpret_cast<const float4*>(x + i);
    uint32_t h0, l0, h1, l1;
    split2h(v.x, v.y, h0, l0);
    split2h(v.z, v.w, h1, l1);
    uint32_t* ph = reinterpret_cast<uint32_t*>(hi + i);
    uint32_t* pl = reinterpret_cast<uint32_t*>(lo + i);
    ph[0] = h0; ph[1] = h1;
    pl[0] = l0; pl[1] = l1;
}

__global__ __launch_bounds__(256) void cvt_w16(
    const float* __restrict__ x, __half* __restrict__ o, int n, float scale)
{
    int i = (blockIdx.x * 256 + threadIdx.x) * 4;
    if (i >= n) return;
    float4 v = *reinterpret_cast<const float4*>(x + i);
    uint32_t* p = reinterpret_cast<uint32_t*>(o + i);
    p[0] = pack2h(v.x * scale, v.y * scale);
    p[1] = pack2h(v.z * scale, v.w * scale);
}

__global__ __launch_bounds__(256) void cvt_split(
    const float* __restrict__ x, __nv_bfloat16* __restrict__ hi,
    __nv_bfloat16* __restrict__ lo, int n)
{
    int i = (blockIdx.x * 256 + threadIdx.x) * 4;
    if (i >= n) return;
    float4 v = *reinterpret_cast<const float4*>(x + i);
    uint32_t h0, l0, h1, l1;
    split2(v.x, v.y, h0, l0);
    split2(v.z, v.w, h1, l1);
    uint32_t* ph = reinterpret_cast<uint32_t*>(hi + i);
    uint32_t* pl = reinterpret_cast<uint32_t*>(lo + i);
    ph[0] = h0; ph[1] = h1;
    pl[0] = l0; pl[1] = l1;
}

// ---------------------------------------------------------------------------
// QKV projection GEMM (fp16): C = A @ W^T + b.
// A = fp16 hi/lo (2 passes), W = single fp16. 128x128 tile, BK=32, 8 warps,
// cp.async 2-stage. Epilogue: z=0 -> q fp16 hi/lo; z=1 k fp16; z=2 v fp16.
// ---------------------------------------------------------------------------
#define AST    40
#define Q_ARR  10240                 // 128*AST*2
#define Q_STG  (3 * Q_ARR)           // Ah, Al, W
#define Q_SMEM (2 * Q_STG)           // 61440

__device__ __forceinline__ void qkv_issue(
    uint32_t sbase, int st,
    const __half* Ah, const __half* Al, const __half* W,
    int m0, int n0, int kc, int tid)
{
    uint32_t b = sbase + st * Q_STG;
#pragma unroll
    for (int i = 0; i < 2; i++) {
        int chunk = tid + i * 256;
        int row = chunk >> 2;
        int c8 = (chunk & 3) * 8;
        uint32_t so = (uint32_t)(row * AST + c8) * 2;
        size_t offA = (size_t)(m0 + row) * DMODEL + kc + c8;
        size_t offB = (size_t)(n0 + row) * DMODEL + kc + c8;
        cp16(b + so,             Ah + offA);
        cp16(b + Q_ARR + so,     Al + offA);
        cp16(b + 2 * Q_ARR + so, W + offB);
    }
}

__global__ __launch_bounds__(256, 1)
void gemm_qkv16(const __half* __restrict__ Ah, const __half* __restrict__ Al,
                const __half* __restrict__ Wq, const __half* __restrict__ Wk,
                const __half* __restrict__ Wv,
                const float* __restrict__ qb, const float* __restrict__ kb,
                const float* __restrict__ vb,
                __half* __restrict__ Qh, __half* __restrict__ Ql,
                __half* __restrict__ Ko, __half* __restrict__ Vo)
{
    extern __shared__ char smem[];
    const uint32_t sbase = smem_u32(smem);
    const int tid = threadIdx.x;
    const int z = blockIdx.z;
    const __half* W   = (z == 0) ? Wq : (z == 1) ? Wk : Wv;
    const float* bias = (z == 0) ? qb : (z == 1) ? kb : vb;
    const float bscale = (z == 0) ? 0.125f : 1.0f;

    const int m0 = blockIdx.y * 128;
    const int n0 = blockIdx.x * 128;

    const int wid = tid >> 5;
    const int lid = tid & 31;
    const int wr = wid >> 2;
    const int wc = wid & 3;
    const int aRow = lid & 15;
    const int aCol = (lid >> 4) << 3;
    const int bRow = (lid & 7) + ((lid & 16) >> 1);
    const int bCol = ((lid >> 3) & 1) << 3;

    float acc[4][4][4];
#pragma unroll
    for (int i = 0; i < 4; i++)
#pragma unroll
        for (int j = 0; j < 4; j++)
#pragma unroll
            for (int e = 0; e < 4; e++) acc[i][j][e] = 0.f;

    qkv_issue(sbase, 0, Ah, Al, W, m0, n0, 0, tid);
    cp_commit();

    const int nIter = DMODEL >> 5;   // 32
    for (int it = 0; it < nIter; it++) {
        if (it + 1 < nIter) {
            qkv_issue(sbase, (it + 1) & 1, Ah, Al, W, m0, n0, (it + 1) << 5, tid);
            cp_commit();
            cp_wait<1>();
        } else {
            cp_wait<0>();
        }
        __syncthreads();

        const uint32_t bA_h = sbase + (it & 1) * Q_STG;
        const uint32_t bA_l = bA_h + Q_ARR;
        const uint32_t bW   = bA_h + 2 * Q_ARR;

#pragma unroll
        for (int ks = 0; ks < 32; ks += 16) {
            uint32_t ah[4][4], al[4][4];
#pragma unroll
            for (int mi = 0; mi < 4; mi++) {
                uint32_t off = (uint32_t)((wr * 64 + mi * 16 + aRow) * AST + ks + aCol) * 2;
                ldm_x4(ah[mi], bA_h + off);
                ldm_x4(al[mi], bA_l + off);
            }
            uint32_t bw[2][4];
#pragma unroll
            for (int p = 0; p < 2; p++) {
                uint32_t off = (uint32_t)((wc * 32 + p * 16 + bRow) * AST + ks + bCol) * 2;
                ldm_x4(bw[p], bW + off);
            }
#pragma unroll
            for (int mi = 0; mi < 4; mi++)
#pragma unroll
                for (int p = 0; p < 2; p++)
#pragma unroll
                    for (int s = 0; s < 2; s++) {
                        float* d = acc[mi][p * 2 + s];
                        mma_f16(d, ah[mi], bw[p][s * 2], bw[p][s * 2 + 1]);
                        mma_f16(d, al[mi], bw[p][s * 2], bw[p][s * 2 + 1]);
                    }
        }
        __syncthreads();
    }

    // Epilogue: head-major scatter
    const int tq = lid >> 2;
    const int tr = (lid & 3) * 2;
#pragma unroll
    for (int mi = 0; mi < 4; mi++) {
#pragma unroll
        for (int ni = 0; ni < 4; ni++) {
            int gm = m0 + wr * 64 + mi * 16 + tq;
            int gn = n0 + wc * 32 + ni * 8 + tr;
            float2 bb = *reinterpret_cast<const float2*>(bias + gn);
#pragma unroll
            for (int half = 0; half < 2; half++) {
                int row = gm + half * 8;
                float ox = acc[mi][ni][half * 2 + 0] + bb.x * bscale;
                float oy = acc[mi][ni][half * 2 + 1] + bb.y * bscale;
                int s = row >> 1;
                int b = row & 1;
                int h = gn >> 6;
                int dh = gn & 63;
                size_t di = (((size_t)(b * NHEAD + h) * SEQL + s) * DHEAD + dh);
                if (z == 0) {
                    uint32_t hi, lo;
                    split2h(ox, oy, hi, lo);
                    *reinterpret_cast<uint32_t*>(Qh + di) = hi;
                    *reinterpret_cast<uint32_t*>(Ql + di) = lo;
                } else if (z == 1) {
                    *reinterpret_cast<uint32_t*>(Ko + di) = pack2h(ox, oy);
                } else {
                    *reinterpret_cast<uint32_t*>(Vo + di) = pack2h(ox, oy);
                }
            }
        }
    }
}

// ---------------------------------------------------------------------------
// Output projection (bf16 3-pass compensated): fp32 row-major C.
// ---------------------------------------------------------------------------
#define G_ARR  10240
#define G_STG  (4 * G_ARR)
#define G_SMEM (2 * G_STG)   // 81920

__device__ __forceinline__ void out_issue(
    uint32_t sbase, int st,
    const __nv_bfloat16* Ahi, const __nv_bfloat16* Alo,
    const __nv_bfloat16* Bhi, const __nv_bfloat16* Blo,
    int m0, int n0, int kc, int tid)
{
    uint32_t b = sbase + st * G_STG;
#pragma unroll
    for (int i = 0; i < 2; i++) {
        int chunk = tid + i * 256;
        int row = chunk >> 2;
        int c8 = (chunk & 3) * 8;
        uint32_t so = (uint32_t)(row * AST + c8) * 2;
        size_t offA = (size_t)(m0 + row) * DMODEL + kc + c8;
        size_t offB = (size_t)(n0 + row) * DMODEL + kc + c8;
        cp16(b + so,              Ahi + offA);
        cp16(b + G_ARR + so,      Alo + offA);
        cp16(b + 2 * G_ARR + so,  Bhi + offB);
        cp16(b + 3 * G_ARR + so,  Blo + offB);
    }
}

__global__ __launch_bounds__(256, 1)
void gemm_out(const __nv_bfloat16* __restrict__ Ahi, const __nv_bfloat16* __restrict__ Alo,
              const __nv_bfloat16* __restrict__ Bhi, const __nv_bfloat16* __restrict__ Blo,
              const float* __restrict__ bias, float* __restrict__ C)
{
    extern __shared__ char smem[];
    const uint32_t sbase = smem_u32(smem);
    const int tid = threadIdx.x;

    const int m0 = blockIdx.y * 128;
    const int n0 = blockIdx.x * 128;

    const int wid = tid >> 5;
    const int lid = tid & 31;
    const int wr = wid >> 2;
    const int wc = wid & 3;
    const int aRow = lid & 15;
    const int aCol = (lid >> 4) << 3;
    const int bRow = (lid & 7) + ((lid & 16) >> 1);
    const int bCol = ((lid >> 3) & 1) << 3;

    float acc[4][4][4];
#pragma unroll
    for (int i = 0; i < 4; i++)
#pragma unroll
        for (int j = 0; j < 4; j++)
#pragma unroll
            for (int e = 0; e < 4; e++) acc[i][j][e] = 0.f;

    out_issue(sbase, 0, Ahi, Alo, Bhi, Blo, m0, n0, 0, tid);
    cp_commit();

    const int nIter = DMODEL >> 5;
    for (int it = 0; it < nIter; it++) {
        if (it + 1 < nIter) {
            out_issue(sbase, (it + 1) & 1, Ahi, Alo, Bhi, Blo, m0, n0, (it + 1) << 5, tid);
            cp_commit();
            cp_wait<1>();
        } else {
            cp_wait<0>();
        }
        __syncthreads();

        const uint32_t bA_h = sbase + (it & 1) * G_STG;
        const uint32_t bA_l = bA_h + G_ARR;
        const uint32_t bB_h = bA_h + 2 * G_ARR;
        const uint32_t bB_l = bA_h + 3 * G_ARR;

#pragma unroll
        for (int ks = 0; ks < 32; ks += 16) {
            uint32_t ah[4][4], al[4][4];
#pragma unroll
            for (int mi = 0; mi < 4; mi++) {
                uint32_t off = (uint32_t)((wr * 64 + mi * 16 + aRow) * AST + ks + aCol) * 2;
                ldm_x4(ah[mi], bA_h + off);
                ldm_x4(al[mi], bA_l + off);
            }
            uint32_t bh[2][4], bl[2][4];
#pragma unroll
            for (int p = 0; p < 2; p++) {
                uint32_t off = (uint32_t)((wc * 32 + p * 16 + bRow) * AST + ks + bCol) * 2;
                ldm_x4(bh[p], bB_h + off);
                ldm_x4(bl[p], bB_l + off);
            }
#pragma unroll
            for (int mi = 0; mi < 4; mi++)
#pragma unroll
                for (int p = 0; p < 2; p++)
#pragma unroll
                    for (int s = 0; s < 2; s++) {
                        float* d = acc[mi][p * 2 + s];
                        mma_bf16(d, ah[mi], bh[p][s * 2], bh[p][s * 2 + 1]);
                        mma_bf16(d, ah[mi], bl[p][s * 2], bl[p][s * 2 + 1]);
                        mma_bf16(d, al[mi], bh[p][s * 2], bh[p][s * 2 + 1]);
                    }
        }
        __syncthreads();
    }

    const int tq = lid >> 2;
    const int tr = (lid & 3) * 2;
#pragma unroll
    for (int mi = 0; mi < 4; mi++) {
#pragma unroll
        for (int ni = 0; ni < 4; ni++) {
            int gm = m0 + wr * 64 + mi * 16 + tq;
            int gn = n0 + wc * 32 + ni * 8 + tr;
            float2 bb = *reinterpret_cast<const float2*>(bias + gn);
#pragma unroll
            for (int half = 0; half < 2; half++) {
                int row = gm + half * 8;
                float2 o;
                o.x = acc[mi][ni][half * 2 + 0] + bb.x;
                o.y = acc[mi][ni][half * 2 + 1] + bb.y;
                *reinterpret_cast<float2*>(C + (size_t)row * DMODEL + gn) = o;
            }
        }
    }
}

// ---------------------------------------------------------------------------
// fp16 tensor-core causal flash attention (unchanged from R8 except occ 4).
// ---------------------------------------------------------------------------
#define KST    72
#define A_ARR  9216
#define A_STG  (2 * A_ARR)
#define A_SMEM (2 * A_STG)   // 36864

__device__ __forceinline__ void attn_issue(
    uint32_t sbase, int st,
    const __half* kh, const __half* vh, size_t koff, int tid)
{
    uint32_t b = sbase + st * A_STG;
#pragma unroll
    for (int i = tid; i < 512; i += 128) {
        int row = i >> 3, c8 = (i & 7) * 8;
        uint32_t so = (uint32_t)(row * KST + c8) * 2;
        size_t go = koff + row * 64 + c8;
        cp16(b + so,         kh + go);
        cp16(b + A_ARR + so, vh + go);
    }
}

__global__ __launch_bounds__(128, 4) void attn_mma(
    const __half* __restrict__ qh, const __half* __restrict__ ql,
    const __half* __restrict__ kh, const __half* __restrict__ vh,
    __nv_bfloat16* __restrict__ ch, __nv_bfloat16* __restrict__ cl)
{
    extern __shared__ char smem[];
    const uint32_t sbase = smem_u32(smem);

    const int qt  = (int)(gridDim.x - 1) - (int)blockIdx.x;  // long blocks first
    const int bh  = blockIdx.y;
    const int tid = threadIdx.x;
    const int wq  = tid >> 5;
    const int lid = tid & 31;

    const size_t headoff = (size_t)bh * SEQL * DHEAD;

    // stage Q hi/lo into stage-0, load persistent fragments
    {
        const __half* Qh = qh + headoff + (size_t)qt * 64 * DHEAD;
        const __half* Ql = ql + headoff + (size_t)qt * 64 * DHEAD;
#pragma unroll
        for (int i = tid; i < 512; i += 128) {
            int row = i >> 3, c8 = (i & 7) * 8;
            uint32_t so = (uint32_t)(row * KST + c8) * 2;
            *reinterpret_cast<uint4*>(smem + so) =
                *reinterpret_cast<const uint4*>(Qh + row * 64 + c8);
            *reinterpret_cast<uint4*>(smem + A_ARR + so) =
                *reinterpret_cast<const uint4*>(Ql + row * 64 + c8);
        }
    }
    __syncthreads();

    const int aRow = lid & 15;
    const int aCol = (lid >> 4) << 3;
    uint32_t qfh[4][4], qfl[4][4];
#pragma unroll
    for (int ks = 0; ks < 4; ks++) {
        uint32_t off = (uint32_t)((wq * 16 + aRow) * KST + ks * 16 + aCol) * 2;
        ldm_x4(qfh[ks], sbase + off);
        ldm_x4(qfl[ks], sbase + A_ARR + off);
    }
    __syncthreads();

    attn_issue(sbase, 0, kh, vh, headoff, tid);
    cp_commit();

    float O[8][4];
#pragma unroll
    for (int i = 0; i < 8; i++)
#pragma unroll
        for (int e = 0; e < 4; e++) O[i][e] = 0.f;
    float m0 = -1e30f, m1 = -1e30f, l0 = 0.f, l1 = 0.f;

    const int bRow = (lid & 7) + ((lid & 16) >> 1);
    const int bCol = ((lid >> 3) & 1) << 3;
    const int r0 = wq * 16 + (lid >> 2);

    for (int kt = 0; kt <= qt; kt++) {
        if (kt < qt) {
            attn_issue(sbase, (kt + 1) & 1, kh, vh,
                       headoff + (size_t)(kt + 1) * 64 * DHEAD, tid);
            cp_commit();
            cp_wait<1>();
        } else {
            cp_wait<0>();
        }
        __syncthreads();

        const uint32_t bK = sbase + (kt & 1) * A_STG;
        const uint32_t bV = bK + A_ARR;

        float S[8][4];
#pragma unroll
        for (int i = 0; i < 8; i++)
#pragma unroll
            for (int e = 0; e < 4; e++) S[i][e] = 0.f;
#pragma unroll
        for (int ks = 0; ks < 4; ks++) {
#pragma unroll
            for (int ng = 0; ng < 4; ng++) {
                uint32_t kf[4];
                uint32_t off = (uint32_t)((ng * 16 + bRow) * KST + ks * 16 + bCol) * 2;
                ldm_x4(kf, bK + off);
#pragma unroll
                for (int s = 0; s < 2; s++) {
                    float* d = S[ng * 2 + s];
                    mma_f16(d, qfh[ks], kf[s * 2], kf[s * 2 + 1]);
                    mma_f16(d, qfl[ks], kf[s * 2], kf[s * 2 + 1]);
                }
            }
        }

        if (kt == qt) {
#pragma unroll
            for (int ni = 0; ni < 8; ni++) {
                int c = ni * 8 + (lid & 3) * 2;
                if (c > r0)         S[ni][0] = -1e30f;
                if (c + 1 > r0)     S[ni][1] = -1e30f;
                if (c > r0 + 8)     S[ni][2] = -1e30f;
                if (c + 1 > r0 + 8) S[ni][3] = -1e30f;
            }
        }

        float mx0 = -1e30f, mx1 = -1e30f;
#pragma unroll
        for (int ni = 0; ni < 8; ni++) {
            mx0 = fmaxf(mx0, fmaxf(S[ni][0], S[ni][1]));
            mx1 = fmaxf(mx1, fmaxf(S[ni][2], S[ni][3]));
        }
        mx0 = fmaxf(mx0, __shfl_xor_sync(0xffffffffu, mx0, 1));
        mx0 = fmaxf(mx0, __shfl_xor_sync(0xffffffffu, mx0, 2));
        mx1 = fmaxf(mx1, __shfl_xor_sync(0xffffffffu, mx1, 1));
        mx1 = fmaxf(mx1, __shfl_xor_sync(0xffffffffu, mx1, 2));
        float mn0 = fmaxf(m0, mx0), mn1 = fmaxf(m1, mx1);
        float c0 = __expf(m0 - mn0), c1 = __expf(m1 - mn1);
        m0 = mn0; m1 = mn1;

        uint32_t pA[8], pB[8];
        float s0 = 0.f, s1 = 0.f;
#pragma unroll
        for (int ni = 0; ni < 8; ni++) {
            float p0 = __expf(S[ni][0] - m0);
            float p1 = __expf(S[ni][1] - m0);
            float p2 = __expf(S[ni][2] - m1);
            float p3 = __expf(S[ni][3] - m1);
            s0 += p0 + p1;
            s1 += p2 + p3;
            pA[ni] = pack2h(p0, p1);
            pB[ni] = pack2h(p2, p3);
        }
        s0 += __shfl_xor_sync(0xffffffffu, s0, 1);
        s0 += __shfl_xor_sync(0xffffffffu, s0, 2);
        s1 += __shfl_xor_sync(0xffffffffu, s1, 1);
        s1 += __shfl_xor_sync(0xffffffffu, s1, 2);
        l0 = l0 * c0 + s0;
        l1 = l1 * c1 + s1;
#pragma unroll
        for (int ni = 0; ni < 8; ni++) {
            O[ni][0] *= c0; O[ni][1] *= c0;
            O[ni][2] *= c1; O[ni][3] *= c1;
        }

#pragma unroll
        for (int ks = 0; ks < 4; ks++) {
            uint32_t aP[4] = {pA[2 * ks], pB[2 * ks], pA[2 * ks + 1], pB[2 * ks + 1]};
#pragma unroll
            for (int ng = 0; ng < 4; ng++) {
                uint32_t vf[4];
                uint32_t off = (uint32_t)((ks * 16 + (lid & 15)) * KST + ng * 16 + ((lid >> 4) << 3)) * 2;
                ldm_x4_t(vf, bV + off);
#pragma unroll
                for (int s = 0; s < 2; s++)
                    mma_f16(O[ng * 2 + s], aP, vf[s * 2], vf[s * 2 + 1]);
            }
        }
        __syncthreads();
    }

    const float inv0 = 1.f / l0;
    const float inv1 = 1.f / l1;
    const int b = bh >> 4;
    const int h = bh & 15;
    const int sq = qt * 64 + wq * 16 + (lid >> 2);
#pragma unroll
    for (int ni = 0; ni < 8; ni++) {
        int col = h * 64 + ni * 8 + (lid & 3) * 2;
        uint32_t hi, lo;
        split2(O[ni][0] * inv0, O[ni][1] * inv0, hi, lo);
        size_t d0 = (size_t)(sq * BATCH + b) * DMODEL + col;
        *reinterpret_cast<uint32_t*>(ch + d0) = hi;
        *reinterpret_cast<uint32_t*>(cl + d0) = lo;
        split2(O[ni][2] * inv1, O[ni][3] * inv1, hi, lo);
        size_t d1 = (size_t)((sq + 8) * BATCH + b) * DMODEL + col;
        *reinterpret_cast<uint32_t*>(ch + d1) = hi;
        *reinterpret_cast<uint32_t*>(cl + d1) = lo;
    }
}

// ---------------------------------------------------------------------------
// Launch
// ---------------------------------------------------------------------------
extern "C" void kernel_launch(void* const* d_in, const int* in_sizes, int n_in,
                              void* d_out, int out_size)
{
    const float* query = (const float*)d_in[0];
    const float* q_w   = (const float*)d_in[1];
    const float* q_b   = (const float*)d_in[2];
    const float* k_w   = (const float*)d_in[3];
    const float* k_b   = (const float*)d_in[4];
    const float* v_w   = (const float*)d_in[5];
    const float* v_b   = (const float*)d_in[6];
    const float* out_w = (const float*)d_in[7];
    const float* out_b = (const float*)d_in[8];
    float* out = (float*)d_out;

    __half *x16h, *x16l, *qw16, *kw16, *vw16, *qhp, *qlp, *khp, *vhp;
    __nv_bfloat16 *ch, *cl, *owh, *owl;
    cudaGetSymbolAddress((void**)&x16h, g_x16h);
    cudaGetSymbolAddress((void**)&x16l, g_x16l);
    cudaGetSymbolAddress((void**)&qw16, g_qw16);
    cudaGetSymbolAddress((void**)&kw16, g_kw16);
    cudaGetSymbolAddress((void**)&vw16, g_vw16);
    cudaGetSymbolAddress((void**)&qhp, g_qh);
    cudaGetSymbolAddress((void**)&qlp, g_ql);
    cudaGetSymbolAddress((void**)&khp, g_kh);
    cudaGetSymbolAddress((void**)&vhp, g_vh);
    cudaGetSymbolAddress((void**)&ch, g_c_hi);
    cudaGetSymbolAddress((void**)&cl, g_c_lo);
    cudaGetSymbolAddress((void**)&owh, g_ow_hi);
    cudaGetSymbolAddress((void**)&owl, g_ow_lo);

    static bool attr_done = false;
    if (!attr_done) {
        cudaFuncSetAttribute(gemm_qkv16, cudaFuncAttributeMaxDynamicSharedMemorySize, Q_SMEM);
        cudaFuncSetAttribute(gemm_out,  cudaFuncAttributeMaxDynamicSharedMemorySize, G_SMEM);
        cudaFuncSetAttribute(attn_mma,  cudaFuncAttributeMaxDynamicSharedMemorySize, A_SMEM);
        attr_done = true;
    }

    const int nTok = MTOK * DMODEL;      // 4M
    const int nW   = DMODEL * DMODEL;    // 1M
    const float qscale = 0.125f;

    cvt_x16<<<nTok / 1024, 256>>>(query, x16h, x16l, nTok);
    cvt_w16<<<nW / 1024, 256>>>(q_w, qw16, nW, qscale);
    cvt_w16<<<nW / 1024, 256>>>(k_w, kw16, nW, 1.0f);
    cvt_w16<<<nW / 1024, 256>>>(v_w, vw16, nW, 1.0f);
    cvt_split<<<nW / 1024, 256>>>(out_w, owh, owl, nW);

    dim3 gqkv(DMODEL / 128, MTOK / 128, 3);   // (8, 32, 3)
    gemm_qkv16<<<gqkv, 256, Q_SMEM>>>(x16h, x16l, qw16, kw16, vw16,
                                      q_b, k_b, v_b, qhp, qlp, khp, vhp);

    dim3 gattn(SEQL / 64, NBH);               // (32, 32)
    attn_mma<<<gattn, 128, A_SMEM>>>(qhp, qlp, khp, vhp, ch, cl);

    dim3 gout(DMODEL / 128, MTOK / 128);      // (8, 32)
    gemm_out<<<gout, 256, G_SMEM>>>(ch, cl, owh, owl, out_b, out);
}

// round 12
// speedup vs baseline: 1.9485x; 1.6432x over previous
#include <cuda_runtime.h>
#include <cuda_bf16.h>
#include <cuda_fp16.h>
#include <cstdint>

// Problem constants
#define SEQL   2048
#define BATCH  2
#define NHEAD  16
#define DHEAD  64
#define DMODEL 1024
#define MTOK   (SEQL * BATCH)   // 4096 tokens
#define NBH    (BATCH * NHEAD)  // 32

// ---------------------------------------------------------------------------
// Scratch (device globals)
// ---------------------------------------------------------------------------
__device__ __half g_x16h[(size_t)MTOK * DMODEL];
__device__ __half g_x16l[(size_t)MTOK * DMODEL];
__device__ __half g_c16h[(size_t)MTOK * DMODEL];
__device__ __half g_c16l[(size_t)MTOK * DMODEL];
__device__ __half g_qw16[(size_t)DMODEL * DMODEL];
__device__ __half g_kw16[(size_t)DMODEL * DMODEL];
__device__ __half g_vw16[(size_t)DMODEL * DMODEL];
__device__ __half g_ow16[(size_t)DMODEL * DMODEL];
__device__ __half g_qh[(size_t)NBH * SEQL * DHEAD];
__device__ __half g_ql[(size_t)NBH * SEQL * DHEAD];
__device__ __half g_kh[(size_t)NBH * SEQL * DHEAD];
__device__ __half g_vh[(size_t)NBH * SEQL * DHEAD];

// ---------------------------------------------------------------------------
// PTX helpers
// ---------------------------------------------------------------------------
__device__ __forceinline__ uint32_t smem_u32(const void* p) {
    uint32_t a;
    asm("{ .reg .u64 t; cvta.to.shared.u64 t, %1; cvt.u32.u64 %0, t; }"
        : "=r"(a) : "l"(p));
    return a;
}

__device__ __forceinline__ void cp16(uint32_t s, const void* g) {
    asm volatile("cp.async.cg.shared.global [%0], [%1], 16;" :: "r"(s), "l"(g));
}
__device__ __forceinline__ void cp_commit() {
    asm volatile("cp.async.commit_group;" ::: "memory");
}
template <int N>
__device__ __forceinline__ void cp_wait() {
    asm volatile("cp.async.wait_group %0;" :: "n"(N) : "memory");
}

__device__ __forceinline__ void ldm_x4(uint32_t* r, uint32_t addr) {
    asm volatile("ldmatrix.sync.aligned.m8n8.x4.shared.b16 {%0,%1,%2,%3}, [%4];"
                 : "=r"(r[0]), "=r"(r[1]), "=r"(r[2]), "=r"(r[3])
                 : "r"(addr));
}
__device__ __forceinline__ void ldm_x4_t(uint32_t* r, uint32_t addr) {
    asm volatile("ldmatrix.sync.aligned.m8n8.x4.trans.shared.b16 {%0,%1,%2,%3}, [%4];"
                 : "=r"(r[0]), "=r"(r[1]), "=r"(r[2]), "=r"(r[3])
                 : "r"(addr));
}
__device__ __forceinline__ void mma_f16(float* d, const uint32_t* a,
                                        uint32_t b0, uint32_t b1) {
    asm volatile(
        "mma.sync.aligned.m16n8k16.row.col.f32.f16.f16.f32 "
        "{%0,%1,%2,%3}, {%4,%5,%6,%7}, {%8,%9}, {%0,%1,%2,%3};"
        : "+f"(d[0]), "+f"(d[1]), "+f"(d[2]), "+f"(d[3])
        : "r"(a[0]), "r"(a[1]), "r"(a[2]), "r"(a[3]), "r"(b0), "r"(b1));
}

__device__ __forceinline__ uint32_t pack2h(float a, float b) {
    __half2 t = __floats2half2_rn(a, b);
    return *reinterpret_cast<uint32_t*>(&t);
}
__device__ __forceinline__ void split2h(float a, float b, uint32_t& hi, uint32_t& lo) {
    __half ha = __float2half_rn(a);
    __half hb = __float2half_rn(b);
    __half2 t; t.x = ha; t.y = hb;
    hi = *reinterpret_cast<uint32_t*>(&t);
    lo = pack2h(a - __half2float(ha), b - __half2float(hb));
}

// ---------------------------------------------------------------------------
// Conversions
// ---------------------------------------------------------------------------
__global__ __launch_bounds__(256) void cvt_x16(
    const float* __restrict__ x, __half* __restrict__ hi,
    __half* __restrict__ lo, int n)
{
    int i = (blockIdx.x * 256 + threadIdx.x) * 4;
    if (i >= n) return;
    float4 v = *reinterpret_cast<const float4*>(x + i);
    uint32_t h0, l0, h1, l1;
    split2h(v.x, v.y, h0, l0);
    split2h(v.z, v.w, h1, l1);
    uint32_t* ph = reinterpret_cast<uint32_t*>(hi + i);
    uint32_t* pl = reinterpret_cast<uint32_t*>(lo + i);
    ph[0] = h0; ph[1] = h1;
    pl[0] = l0; pl[1] = l1;
}

// Fused: 4 weight matrices -> single fp16 (blockIdx.y selects; idx 0 scaled)
__global__ __launch_bounds__(256) void cvt_w4_16(
    const float* __restrict__ w0, const float* __restrict__ w1,
    const float* __restrict__ w2, const float* __restrict__ w3,
    __half* __restrict__ o0, __half* __restrict__ o1,
    __half* __restrict__ o2, __half* __restrict__ o3, int n)
{
    const int m = blockIdx.y;
    const float* x = (m == 0) ? w0 : (m == 1) ? w1 : (m == 2) ? w2 : w3;
    __half* o      = (m == 0) ? o0 : (m == 1) ? o1 : (m == 2) ? o2 : o3;
    const float scale = (m == 0) ? 0.125f : 1.0f;
    int i = (blockIdx.x * 256 + threadIdx.x) * 4;
    if (i >= n) return;
    float4 v = *reinterpret_cast<const float4*>(x + i);
    uint32_t* p = reinterpret_cast<uint32_t*>(o + i);
    p[0] = pack2h(v.x * scale, v.y * scale);
    p[1] = pack2h(v.z * scale, v.w * scale);
}

// ---------------------------------------------------------------------------
// fp16 GEMM core: C = A @ W^T. A = fp16 hi/lo (2 passes), W = single fp16.
// 128x128 CTA tile, BK=32, 8 warps, cp.async 3-stage, ONE barrier/iter.
// ---------------------------------------------------------------------------
#define AST    40
#define Q_ARR  10240                 // 128*AST*2
#define Q_STG  (3 * Q_ARR)           // Ah, Al, W
#define Q_SMEM (3 * Q_STG)           // 92160 (3 stages)
#define NITER  (DMODEL / 32)         // 32

__device__ __forceinline__ void g16_issue(
    uint32_t sbase, int st,
    const __half* Ah, const __half* Al, const __half* W,
    int m0, int n0, int kc, int tid)
{
    uint32_t b = sbase + st * Q_STG;
#pragma unroll
    for (int i = 0; i < 2; i++) {
        int chunk = tid + i * 256;
        int row = chunk >> 2;
        int c8 = (chunk & 3) * 8;
        uint32_t so = (uint32_t)(row * AST + c8) * 2;
        size_t offA = (size_t)(m0 + row) * DMODEL + kc + c8;
        size_t offB = (size_t)(n0 + row) * DMODEL + kc + c8;
        cp16(b + so,             Ah + offA);
        cp16(b + Q_ARR + so,     Al + offA);
        cp16(b + 2 * Q_ARR + so, W + offB);
    }
}

__device__ __forceinline__ void g16_core(
    uint32_t sbase,
    const __half* Ah, const __half* Al, const __half* W,
    int m0, int n0, int tid, float acc[4][4][4])
{
    const int wid = tid >> 5;
    const int lid = tid & 31;
    const int wr = wid >> 2;
    const int wc = wid & 3;
    const int aRow = lid & 15;
    const int aCol = (lid >> 4) << 3;
    const int bRow = (lid & 7) + ((lid & 16) >> 1);
    const int bCol = ((lid >> 3) & 1) << 3;

    g16_issue(sbase, 0, Ah, Al, W, m0, n0, 0, tid);
    cp_commit();
    g16_issue(sbase, 1, Ah, Al, W, m0, n0, 32, tid);
    cp_commit();

    int st = 0;                  // stage of iteration it (rotates 0,1,2)
    for (int it = 0; it < NITER; it++) {
        if (it < NITER - 1) cp_wait<1>(); else cp_wait<0>();
        __syncthreads();         // all warps done reading stage st+2 (iter it-1)

        if (it + 2 < NITER) {
            int wst = st + 2; if (wst >= 3) wst -= 3;
            g16_issue(sbase, wst, Ah, Al, W, m0, n0, (it + 2) << 5, tid);
            cp_commit();
        }

        const uint32_t bA_h = sbase + st * Q_STG;
        const uint32_t bA_l = bA_h + Q_ARR;
        const uint32_t bW   = bA_h + 2 * Q_ARR;

#pragma unroll
        for (int ks = 0; ks < 32; ks += 16) {
            uint32_t ah[4][4], al[4][4];
#pragma unroll
            for (int mi = 0; mi < 4; mi++) {
                uint32_t off = (uint32_t)((wr * 64 + mi * 16 + aRow) * AST + ks + aCol) * 2;
                ldm_x4(ah[mi], bA_h + off);
                ldm_x4(al[mi], bA_l + off);
            }
            uint32_t bw[2][4];
#pragma unroll
            for (int p = 0; p < 2; p++) {
                uint32_t off = (uint32_t)((wc * 32 + p * 16 + bRow) * AST + ks + bCol) * 2;
                ldm_x4(bw[p], bW + off);
            }
#pragma unroll
            for (int mi = 0; mi < 4; mi++)
#pragma unroll
                for (int p = 0; p < 2; p++)
#pragma unroll
                    for (int s = 0; s < 2; s++) {
                        float* d = acc[mi][p * 2 + s];
                        mma_f16(d, ah[mi], bw[p][s * 2], bw[p][s * 2 + 1]);
                        mma_f16(d, al[mi], bw[p][s * 2], bw[p][s * 2 + 1]);
                    }
        }
        if (++st >= 3) st -= 3;
    }
}

// QKV projection: grid (8, 32, 3); epilogue scatters head-major fp16.
__global__ __launch_bounds__(256, 1)
void gemm_qkv16(const __half* __restrict__ Ah, const __half* __restrict__ Al,
                const __half* __restrict__ Wq, const __half* __restrict__ Wk,
                const __half* __restrict__ Wv,
                const float* __restrict__ qb, const float* __restrict__ kb,
                const float* __restrict__ vb,
                __half* __restrict__ Qh, __half* __restrict__ Ql,
                __half* __restrict__ Ko, __half* __restrict__ Vo)
{
    extern __shared__ char smem[];
    const uint32_t sbase = smem_u32(smem);
    const int tid = threadIdx.x;
    const int z = blockIdx.z;
    const __half* W   = (z == 0) ? Wq : (z == 1) ? Wk : Wv;
    const float* bias = (z == 0) ? qb : (z == 1) ? kb : vb;
    const float bscale = (z == 0) ? 0.125f : 1.0f;

    const int m0 = blockIdx.y * 128;
    const int n0 = blockIdx.x * 128;

    float acc[4][4][4];
#pragma unroll
    for (int i = 0; i < 4; i++)
#pragma unroll
        for (int j = 0; j < 4; j++)
#pragma unroll
            for (int e = 0; e < 4; e++) acc[i][j][e] = 0.f;

    g16_core(sbase, Ah, Al, W, m0, n0, tid, acc);

    const int wid = tid >> 5;
    const int lid = tid & 31;
    const int wr = wid >> 2;
    const int wc = wid & 3;
    const int tq = lid >> 2;
    const int tr = (lid & 3) * 2;
#pragma unroll
    for (int mi = 0; mi < 4; mi++) {
#pragma unroll
        for (int ni = 0; ni < 4; ni++) {
            int gm = m0 + wr * 64 + mi * 16 + tq;
            int gn = n0 + wc * 32 + ni * 8 + tr;
            float2 bb = *reinterpret_cast<const float2*>(bias + gn);
#pragma unroll
            for (int half = 0; half < 2; half++) {
                int row = gm + half * 8;
                float ox = acc[mi][ni][half * 2 + 0] + bb.x * bscale;
                float oy = acc[mi][ni][half * 2 + 1] + bb.y * bscale;
                int s = row >> 1;
                int b = row & 1;
                int h = gn >> 6;
                int dh = gn & 63;
                size_t di = (((size_t)(b * NHEAD + h) * SEQL + s) * DHEAD + dh);
                if (z == 0) {
                    uint32_t hi, lo;
                    split2h(ox, oy, hi, lo);
                    *reinterpret_cast<uint32_t*>(Qh + di) = hi;
                    *reinterpret_cast<uint32_t*>(Ql + di) = lo;
                } else if (z == 1) {
                    *reinterpret_cast<uint32_t*>(Ko + di) = pack2h(ox, oy);
                } else {
                    *reinterpret_cast<uint32_t*>(Vo + di) = pack2h(ox, oy);
                }
            }
        }
    }
}

// Output projection: ctx fp16 hi/lo (2-pass) x out_w fp16 -> fp32 row-major.
__global__ __launch_bounds__(256, 1)
void gemm_out16(const __half* __restrict__ Ah, const __half* __restrict__ Al,
                const __half* __restrict__ W,
                const float* __restrict__ bias, float* __restrict__ C)
{
    extern __shared__ char smem[];
    const uint32_t sbase = smem_u32(smem);
    const int tid = threadIdx.x;

    const int m0 = blockIdx.y * 128;
    const int n0 = blockIdx.x * 128;

    float acc[4][4][4];
#pragma unroll
    for (int i = 0; i < 4; i++)
#pragma unroll
        for (int j = 0; j < 4; j++)
#pragma unroll
            for (int e = 0; e < 4; e++) acc[i][j][e] = 0.f;

    g16_core(sbase, Ah, Al, W, m0, n0, tid, acc);

    const int wid = tid >> 5;
    const int lid = tid & 31;
    const int wr = wid >> 2;
    const int wc = wid & 3;
    const int tq = lid >> 2;
    const int tr = (lid & 3) * 2;
#pragma unroll
    for (int mi = 0; mi < 4; mi++) {
#pragma unroll
        for (int ni = 0; ni < 4; ni++) {
            int gm = m0 + wr * 64 + mi * 16 + tq;
            int gn = n0 + wc * 32 + ni * 8 + tr;
            float2 bb = *reinterpret_cast<const float2*>(bias + gn);
#pragma unroll
            for (int half = 0; half < 2; half++) {
                int row = gm + half * 8;
                float2 o;
                o.x = acc[mi][ni][half * 2 + 0] + bb.x;
                o.y = acc[mi][ni][half * 2 + 1] + bb.y;
                *reinterpret_cast<float2*>(C + (size_t)row * DMODEL + gn) = o;
            }
        }
    }
}

// ---------------------------------------------------------------------------
// fp16 tensor-core causal flash attention, cp.async 2-stage, 1 barrier/iter.
// Block: 128 threads (4 warps), 64 queries of one (b,h). Key tile 64.
// ---------------------------------------------------------------------------
#define KST    72
#define A_ARR  9216
#define A_STG  (2 * A_ARR)
#define A_SMEM (2 * A_STG)   // 36864

__device__ __forceinline__ void attn_issue(
    uint32_t sbase, int st,
    const __half* kh, const __half* vh, size_t koff, int tid)
{
    uint32_t b = sbase + st * A_STG;
#pragma unroll
    for (int i = tid; i < 512; i += 128) {
        int row = i >> 3, c8 = (i & 7) * 8;
        uint32_t so = (uint32_t)(row * KST + c8) * 2;
        size_t go = koff + row * 64 + c8;
        cp16(b + so,         kh + go);
        cp16(b + A_ARR + so, vh + go);
    }
}

__global__ __launch_bounds__(128, 4) void attn_mma(
    const __half* __restrict__ qh, const __half* __restrict__ ql,
    const __half* __restrict__ kh, const __half* __restrict__ vh,
    __half* __restrict__ ch, __half* __restrict__ cl)
{
    extern __shared__ char smem[];
    const uint32_t sbase = smem_u32(smem);

    const int qt  = (int)(gridDim.x - 1) - (int)blockIdx.x;  // long blocks first
    const int bh  = blockIdx.y;
    const int tid = threadIdx.x;
    const int wq  = tid >> 5;
    const int lid = tid & 31;

    const size_t headoff = (size_t)bh * SEQL * DHEAD;

    // stage Q hi/lo into stage-0 buffers, load persistent fragments
    {
        const __half* Qh = qh + headoff + (size_t)qt * 64 * DHEAD;
        const __half* Ql = ql + headoff + (size_t)qt * 64 * DHEAD;
#pragma unroll
        for (int i = tid; i < 512; i += 128) {
            int row = i >> 3, c8 = (i & 7) * 8;
            uint32_t so = (uint32_t)(row * KST + c8) * 2;
            *reinterpret_cast<uint4*>(smem + so) =
                *reinterpret_cast<const uint4*>(Qh + row * 64 + c8);
            *reinterpret_cast<uint4*>(smem + A_ARR + so) =
                *reinterpret_cast<const uint4*>(Ql + row * 64 + c8);
        }
    }
    __syncthreads();

    const int aRow = lid & 15;
    const int aCol = (lid >> 4) << 3;
    uint32_t qfh[4][4], qfl[4][4];
#pragma unroll
    for (int ks = 0; ks < 4; ks++) {
        uint32_t off = (uint32_t)((wq * 16 + aRow) * KST + ks * 16 + aCol) * 2;
        ldm_x4(qfh[ks], sbase + off);
        ldm_x4(qfl[ks], sbase + A_ARR + off);
    }
    __syncthreads();   // Q fragments read before stage-0 is overwritten

    attn_issue(sbase, 0, kh, vh, headoff, tid);
    cp_commit();

    float O[8][4];
#pragma unroll
    for (int i = 0; i < 8; i++)
#pragma unroll
        for (int e = 0; e < 4; e++) O[i][e] = 0.f;
    float m0 = -1e30f, m1 = -1e30f, l0 = 0.f, l1 = 0.f;

    const int bRow = (lid & 7) + ((lid & 16) >> 1);
    const int bCol = ((lid >> 3) & 1) << 3;
    const int r0 = wq * 16 + (lid >> 2);

    for (int kt = 0; kt <= qt; kt++) {
        cp_wait<0>();          // stage kt landed
        __syncthreads();       // all warps done with iter kt-1 (incl. buffer kt+1)
        if (kt < qt) {         // prefetch kt+1 into the other buffer
            attn_issue(sbase, (kt + 1) & 1, kh, vh,
                       headoff + (size_t)(kt + 1) * 64 * DHEAD, tid);
            cp_commit();
        }

        const uint32_t bK = sbase + (kt & 1) * A_STG;
        const uint32_t bV = bK + A_ARR;

        float S[8][4];
#pragma unroll
        for (int i = 0; i < 8; i++)
#pragma unroll
            for (int e = 0; e < 4; e++) S[i][e] = 0.f;
#pragma unroll
        for (int ks = 0; ks < 4; ks++) {
#pragma unroll
            for (int ng = 0; ng < 4; ng++) {
                uint32_t kf[4];
                uint32_t off = (uint32_t)((ng * 16 + bRow) * KST + ks * 16 + bCol) * 2;
                ldm_x4(kf, bK + off);
#pragma unroll
                for (int s = 0; s < 2; s++) {
                    float* d = S[ng * 2 + s];
                    mma_f16(d, qfh[ks], kf[s * 2], kf[s * 2 + 1]);
                    mma_f16(d, qfl[ks], kf[s * 2], kf[s * 2 + 1]);
                }
            }
        }

        if (kt == qt) {
#pragma unroll
            for (int ni = 0; ni < 8; ni++) {
                int c = ni * 8 + (lid & 3) * 2;
                if (c > r0)         S[ni][0] = -1e30f;
                if (c + 1 > r0)     S[ni][1] = -1e30f;
                if (c > r0 + 8)     S[ni][2] = -1e30f;
                if (c + 1 > r0 + 8) S[ni][3] = -1e30f;
            }
        }

        float mx0 = -1e30f, mx1 = -1e30f;
#pragma unroll
        for (int ni = 0; ni < 8; ni++) {
            mx0 = fmaxf(mx0, fmaxf(S[ni][0], S[ni][1]));
            mx1 = fmaxf(mx1, fmaxf(S[ni][2], S[ni][3]));
        }
        mx0 = fmaxf(mx0, __shfl_xor_sync(0xffffffffu, mx0, 1));
        mx0 = fmaxf(mx0, __shfl_xor_sync(0xffffffffu, mx0, 2));
        mx1 = fmaxf(mx1, __shfl_xor_sync(0xffffffffu, mx1, 1));
        mx1 = fmaxf(mx1, __shfl_xor_sync(0xffffffffu, mx1, 2));
        float mn0 = fmaxf(m0, mx0), mn1 = fmaxf(m1, mx1);
        float c0 = __expf(m0 - mn0), c1 = __expf(m1 - mn1);
        m0 = mn0; m1 = mn1;

        uint32_t pA[8], pB[8];
        float s0 = 0.f, s1 = 0.f;
#pragma unroll
        for (int ni = 0; ni < 8; ni++) {
            float p0 = __expf(S[ni][0] - m0);
            float p1 = __expf(S[ni][1] - m0);
            float p2 = __expf(S[ni][2] - m1);
            float p3 = __expf(S[ni][3] - m1);
            s0 += p0 + p1;
            s1 += p2 + p3;
            pA[ni] = pack2h(p0, p1);
            pB[ni] = pack2h(p2, p3);
        }
        s0 += __shfl_xor_sync(0xffffffffu, s0, 1);
        s0 += __shfl_xor_sync(0xffffffffu, s0, 2);
        s1 += __shfl_xor_sync(0xffffffffu, s1, 1);
        s1 += __shfl_xor_sync(0xffffffffu, s1, 2);
        l0 = l0 * c0 + s0;
        l1 = l1 * c1 + s1;
#pragma unroll
        for (int ni = 0; ni < 8; ni++) {
            O[ni][0] *= c0; O[ni][1] *= c0;
            O[ni][2] *= c1; O[ni][3] *= c1;
        }

#pragma unroll
        for (int ks = 0; ks < 4; ks++) {
            uint32_t aP[4] = {pA[2 * ks], pB[2 * ks], pA[2 * ks + 1], pB[2 * ks + 1]};
#pragma unroll
            for (int ng = 0; ng < 4; ng++) {
                uint32_t vf[4];
                uint32_t off = (uint32_t)((ks * 16 + (lid & 15)) * KST + ng * 16 + ((lid >> 4) << 3)) * 2;
                ldm_x4_t(vf, bV + off);
#pragma unroll
                for (int s = 0; s < 2; s++)
                    mma_f16(O[ng * 2 + s], aP, vf[s * 2], vf[s * 2 + 1]);
            }
        }
        // no trailing barrier: next iter's top barrier orders buffer reuse
    }

    // epilogue: normalize, split to fp16 hi/lo, scatter to ctx [t][d]
    const float inv0 = 1.f / l0;
    const float inv1 = 1.f / l1;
    const int b = bh >> 4;
    const int h = bh & 15;
    const int sq = qt * 64 + wq * 16 + (lid >> 2);
#pragma unroll
    for (int ni = 0; ni < 8; ni++) {
        int col = h * 64 + ni * 8 + (lid & 3) * 2;
        uint32_t hi, lo;
        split2h(O[ni][0] * inv0, O[ni][1] * inv0, hi, lo);
        size_t d0 = (size_t)(sq * BATCH + b) * DMODEL + col;
        *reinterpret_cast<uint32_t*>(ch + d0) = hi;
        *reinterpret_cast<uint32_t*>(cl + d0) = lo;
        split2h(O[ni][2] * inv1, O[ni][3] * inv1, hi, lo);
        size_t d1 = (size_t)((sq + 8) * BATCH + b) * DMODEL + col;
        *reinterpret_cast<uint32_t*>(ch + d1) = hi;
        *reinterpret_cast<uint32_t*>(cl + d1) = lo;
    }
}

// ---------------------------------------------------------------------------
// Launch
// ---------------------------------------------------------------------------
extern "C" void kernel_launch(void* const* d_in, const int* in_sizes, int n_in,
                              void* d_out, int out_size)
{
    const float* query = (const float*)d_in[0];
    const float* q_w   = (const float*)d_in[1];
    const float* q_b   = (const float*)d_in[2];
    const float* k_w   = (const float*)d_in[3];
    const float* k_b   = (const float*)d_in[4];
    const float* v_w   = (const float*)d_in[5];
    const float* v_b   = (const float*)d_in[6];
    const float* out_w = (const float*)d_in[7];
    const float* out_b = (const float*)d_in[8];
    float* out = (float*)d_out;

    __half *x16h, *x16l, *c16h, *c16l;
    __half *qw16, *kw16, *vw16, *ow16, *qhp, *qlp, *khp, *vhp;
    cudaGetSymbolAddress((void**)&x16h, g_x16h);
    cudaGetSymbolAddress((void**)&x16l, g_x16l);
    cudaGetSymbolAddress((void**)&c16h, g_c16h);
    cudaGetSymbolAddress((void**)&c16l, g_c16l);
    cudaGetSymbolAddress((void**)&qw16, g_qw16);
    cudaGetSymbolAddress((void**)&kw16, g_kw16);
    cudaGetSymbolAddress((void**)&vw16, g_vw16);
    cudaGetSymbolAddress((void**)&ow16, g_ow16);
    cudaGetSymbolAddress((void**)&qhp, g_qh);
    cudaGetSymbolAddress((void**)&qlp, g_ql);
    cudaGetSymbolAddress((void**)&khp, g_kh);
    cudaGetSymbolAddress((void**)&vhp, g_vh);

    static bool attr_done = false;
    if (!attr_done) {
        cudaFuncSetAttribute(gemm_qkv16, cudaFuncAttributeMaxDynamicSharedMemorySize, Q_SMEM);
        cudaFuncSetAttribute(gemm_out16, cudaFuncAttributeMaxDynamicSharedMemorySize, Q_SMEM);
        cudaFuncSetAttribute(attn_mma,   cudaFuncAttributeMaxDynamicSharedMemorySize, A_SMEM);
        attr_done = true;
    }

    const int nTok = MTOK * DMODEL;      // 4M
    const int nW   = DMODEL * DMODEL;    // 1M

    cvt_x16<<<nTok / 1024, 256>>>(query, x16h, x16l, nTok);
    dim3 gw(nW / 1024, 4);
    cvt_w4_16<<<gw, 256>>>(q_w, k_w, v_w, out_w, qw16, kw16, vw16, ow16, nW);

    dim3 gqkv(DMODEL / 128, MTOK / 128, 3);   // (8, 32, 3)
    gemm_qkv16<<<gqkv, 256, Q_SMEM>>>(x16h, x16l, qw16, kw16, vw16,
                                      q_b, k_b, v_b, qhp, qlp, khp, vhp);

    dim3 gattn(SEQL / 64, NBH);               // (32, 32)
    attn_mma<<<gattn, 128, A_SMEM>>>(qhp, qlp, khp, vhp, c16h, c16l);

    dim3 gout(DMODEL / 128, MTOK / 128);      // (8, 32)
    gemm_out16<<<gout, 256, Q_SMEM>>>(c16h, c16l, ow16, out_b, out);
}

// round 16
// speedup vs baseline: 2.0022x; 1.0276x over previous
#include <cuda_runtime.h>
#include <cuda_bf16.h>
#include <cuda_fp16.h>
#include <cstdint>

// Problem constants
#define SEQL   2048
#define BATCH  2
#define NHEAD  16
#define DHEAD  64
#define DMODEL 1024
#define MTOK   (SEQL * BATCH)   // 4096 tokens
#define NBH    (BATCH * NHEAD)  // 32

// ---------------------------------------------------------------------------
// Scratch (device globals)
// ---------------------------------------------------------------------------
__device__ __half g_x16h[(size_t)MTOK * DMODEL];
__device__ __half g_x16l[(size_t)MTOK * DMODEL];
__device__ __half g_c16h[(size_t)MTOK * DMODEL];
__device__ __half g_c16l[(size_t)MTOK * DMODEL];
__device__ __half g_qw16[(size_t)DMODEL * DMODEL];
__device__ __half g_kw16[(size_t)DMODEL * DMODEL];
__device__ __half g_vw16[(size_t)DMODEL * DMODEL];
__device__ __half g_ow16[(size_t)DMODEL * DMODEL];
__device__ __half g_qh[(size_t)NBH * SEQL * DHEAD];
__device__ __half g_ql[(size_t)NBH * SEQL * DHEAD];
__device__ __half g_kh[(size_t)NBH * SEQL * DHEAD];
__device__ __half g_vh[(size_t)NBH * SEQL * DHEAD];

// ---------------------------------------------------------------------------
// PTX helpers
// ---------------------------------------------------------------------------
__device__ __forceinline__ uint32_t smem_u32(const void* p) {
    uint32_t a;
    asm("{ .reg .u64 t; cvta.to.shared.u64 t, %1; cvt.u32.u64 %0, t; }"
        : "=r"(a) : "l"(p));
    return a;
}

__device__ __forceinline__ void cp16(uint32_t s, const void* g) {
    asm volatile("cp.async.cg.shared.global [%0], [%1], 16;" :: "r"(s), "l"(g));
}
__device__ __forceinline__ void cp_commit() {
    asm volatile("cp.async.commit_group;" ::: "memory");
}
template <int N>
__device__ __forceinline__ void cp_wait() {
    asm volatile("cp.async.wait_group %0;" :: "n"(N) : "memory");
}

__device__ __forceinline__ void ldm_x4(uint32_t* r, uint32_t addr) {
    asm volatile("ldmatrix.sync.aligned.m8n8.x4.shared.b16 {%0,%1,%2,%3}, [%4];"
                 : "=r"(r[0]), "=r"(r[1]), "=r"(r[2]), "=r"(r[3])
                 : "r"(addr));
}
__device__ __forceinline__ void ldm_x4_t(uint32_t* r, uint32_t addr) {
    asm volatile("ldmatrix.sync.aligned.m8n8.x4.trans.shared.b16 {%0,%1,%2,%3}, [%4];"
                 : "=r"(r[0]), "=r"(r[1]), "=r"(r[2]), "=r"(r[3])
                 : "r"(addr));
}
__device__ __forceinline__ void mma_f16(float* d, const uint32_t* a,
                                        uint32_t b0, uint32_t b1) {
    asm volatile(
        "mma.sync.aligned.m16n8k16.row.col.f32.f16.f16.f32 "
        "{%0,%1,%2,%3}, {%4,%5,%6,%7}, {%8,%9}, {%0,%1,%2,%3};"
        : "+f"(d[0]), "+f"(d[1]), "+f"(d[2]), "+f"(d[3])
        : "r"(a[0]), "r"(a[1]), "r"(a[2]), "r"(a[3]), "r"(b0), "r"(b1));
}

__device__ __forceinline__ uint32_t pack2h(float a, float b) {
    __half2 t = __floats2half2_rn(a, b);
    return *reinterpret_cast<uint32_t*>(&t);
}
__device__ __forceinline__ void split2h(float a, float b, uint32_t& hi, uint32_t& lo) {
    __half ha = __float2half_rn(a);
    __half hb = __float2half_rn(b);
    __half2 t; t.x = ha; t.y = hb;
    hi = *reinterpret_cast<uint32_t*>(&t);
    lo = pack2h(a - __half2float(ha), b - __half2float(hb));
}

// ---------------------------------------------------------------------------
// Conversions
// ---------------------------------------------------------------------------
__global__ __launch_bounds__(256) void cvt_x16(
    const float* __restrict__ x, __half* __restrict__ hi,
    __half* __restrict__ lo, int n)
{
    int i = (blockIdx.x * 256 + threadIdx.x) * 4;
    if (i >= n) return;
    float4 v = *reinterpret_cast<const float4*>(x + i);
    uint32_t h0, l0, h1, l1;
    split2h(v.x, v.y, h0, l0);
    split2h(v.z, v.w, h1, l1);
    uint32_t* ph = reinterpret_cast<uint32_t*>(hi + i);
    uint32_t* pl = reinterpret_cast<uint32_t*>(lo + i);
    ph[0] = h0; ph[1] = h1;
    pl[0] = l0; pl[1] = l1;
}

__global__ __launch_bounds__(256) void cvt_w4_16(
    const float* __restrict__ w0, const float* __restrict__ w1,
    const float* __restrict__ w2, const float* __restrict__ w3,
    __half* __restrict__ o0, __half* __restrict__ o1,
    __half* __restrict__ o2, __half* __restrict__ o3, int n)
{
    const int m = blockIdx.y;
    const float* x = (m == 0) ? w0 : (m == 1) ? w1 : (m == 2) ? w2 : w3;
    __half* o      = (m == 0) ? o0 : (m == 1) ? o1 : (m == 2) ? o2 : o3;
    const float scale = (m == 0) ? 0.125f : 1.0f;
    int i = (blockIdx.x * 256 + threadIdx.x) * 4;
    if (i >= n) return;
    float4 v = *reinterpret_cast<const float4*>(x + i);
    uint32_t* p = reinterpret_cast<uint32_t*>(o + i);
    p[0] = pack2h(v.x * scale, v.y * scale);
    p[1] = pack2h(v.z * scale, v.w * scale);
}

// ---------------------------------------------------------------------------
// fp16 GEMM core: C = A @ W^T. A = fp16 hi/lo (2 passes), W = single fp16.
// 128x128 CTA tile, BK=32, 512 threads (16 warps, 32x32 warp tiles),
// cp.async 2-stage, one barrier per iteration.
// ---------------------------------------------------------------------------
#define AST    40
#define Q_ARR  10240                 // 128*AST*2
#define Q_STG  (3 * Q_ARR)           // Ah, Al, W
#define Q_SMEM (2 * Q_STG)           // 61440
#define NITER  (DMODEL / 32)         // 32

__device__ __forceinline__ void g16_issue(
    uint32_t sbase, int st,
    const __half* Ah, const __half* Al, const __half* W,
    int m0, int n0, int kc, int tid)
{
    uint32_t b = sbase + st * Q_STG;
    int row = tid >> 2;              // 0..127
    int c8 = (tid & 3) * 8;
    uint32_t so = (uint32_t)(row * AST + c8) * 2;
    size_t offA = (size_t)(m0 + row) * DMODEL + kc + c8;
    size_t offB = (size_t)(n0 + row) * DMODEL + kc + c8;
    cp16(b + so,             Ah + offA);
    cp16(b + Q_ARR + so,     Al + offA);
    cp16(b + 2 * Q_ARR + so, W + offB);
}

__device__ __forceinline__ void g16_core(
    uint32_t sbase,
    const __half* Ah, const __half* Al, const __half* W,
    int m0, int n0, int tid, float acc[2][4][4])
{
    const int wid = tid >> 5;
    const int lid = tid & 31;
    const int wr = wid >> 2;         // 0..3 : 32-row strip
    const int wc = wid & 3;          // 0..3 : 32-col strip
    const int aRow = lid & 15;
    const int aCol = (lid >> 4) << 3;
    const int bRow = (lid & 7) + ((lid & 16) >> 1);
    const int bCol = ((lid >> 3) & 1) << 3;

    g16_issue(sbase, 0, Ah, Al, W, m0, n0, 0, tid);
    cp_commit();

    for (int it = 0; it < NITER; it++) {
        cp_wait<0>();
        __syncthreads();
        if (it + 1 < NITER) {
            g16_issue(sbase, (it + 1) & 1, Ah, Al, W, m0, n0, (it + 1) << 5, tid);
            cp_commit();
        }

        const uint32_t bA_h = sbase + (it & 1) * Q_STG;
        const uint32_t bA_l = bA_h + Q_ARR;
        const uint32_t bW   = bA_h + 2 * Q_ARR;

#pragma unroll
        for (int ks = 0; ks < 32; ks += 16) {
            uint32_t ah[2][4], al[2][4];
#pragma unroll
            for (int mi = 0; mi < 2; mi++) {
                uint32_t off = (uint32_t)((wr * 32 + mi * 16 + aRow) * AST + ks + aCol) * 2;
                ldm_x4(ah[mi], bA_h + off);
                ldm_x4(al[mi], bA_l + off);
            }
            uint32_t bw[2][4];
#pragma unroll
            for (int p = 0; p < 2; p++) {
                uint32_t off = (uint32_t)((wc * 32 + p * 16 + bRow) * AST + ks + bCol) * 2;
                ldm_x4(bw[p], bW + off);
            }
#pragma unroll
            for (int mi = 0; mi < 2; mi++)
#pragma unroll
                for (int p = 0; p < 2; p++)
#pragma unroll
                    for (int s = 0; s < 2; s++) {
                        float* d = acc[mi][p * 2 + s];
                        mma_f16(d, ah[mi], bw[p][s * 2], bw[p][s * 2 + 1]);
                        mma_f16(d, al[mi], bw[p][s * 2], bw[p][s * 2 + 1]);
                    }
        }
    }
}

// QKV projection: grid (8, 32, 3), 512 threads.
__global__ __launch_bounds__(512, 1)
void gemm_qkv16(const __half* __restrict__ Ah, const __half* __restrict__ Al,
                const __half* __restrict__ Wq, const __half* __restrict__ Wk,
                const __half* __restrict__ Wv,
                const float* __restrict__ qb, const float* __restrict__ kb,
                const float* __restrict__ vb,
                __half* __restrict__ Qh, __half* __restrict__ Ql,
                __half* __restrict__ Ko, __half* __restrict__ Vo)
{
    extern __shared__ char smem[];
    const uint32_t sbase = smem_u32(smem);
    const int tid = threadIdx.x;
    const int z = blockIdx.z;
    const __half* W   = (z == 0) ? Wq : (z == 1) ? Wk : Wv;
    const float* bias = (z == 0) ? qb : (z == 1) ? kb : vb;
    const float bscale = (z == 0) ? 0.125f : 1.0f;

    const int m0 = blockIdx.y * 128;
    const int n0 = blockIdx.x * 128;

    float acc[2][4][4];
#pragma unroll
    for (int i = 0; i < 2; i++)
#pragma unroll
        for (int j = 0; j < 4; j++)
#pragma unroll
            for (int e = 0; e < 4; e++) acc[i][j][e] = 0.f;

    g16_core(sbase, Ah, Al, W, m0, n0, tid, acc);

    const int wid = tid >> 5;
    const int lid = tid & 31;
    const int wr = wid >> 2;
    const int wc = wid & 3;
    const int tq = lid >> 2;
    const int tr = (lid & 3) * 2;
#pragma unroll
    for (int mi = 0; mi < 2; mi++) {
#pragma unroll
        for (int ni = 0; ni < 4; ni++) {
            int gm = m0 + wr * 32 + mi * 16 + tq;
            int gn = n0 + wc * 32 + ni * 8 + tr;
            float2 bb = *reinterpret_cast<const float2*>(bias + gn);
#pragma unroll
            for (int half = 0; half < 2; half++) {
                int row = gm + half * 8;
                float ox = acc[mi][ni][half * 2 + 0] + bb.x * bscale;
                float oy = acc[mi][ni][half * 2 + 1] + bb.y * bscale;
                int s = row >> 1;
                int b = row & 1;
                int h = gn >> 6;
                int dh = gn & 63;
                size_t di = (((size_t)(b * NHEAD + h) * SEQL + s) * DHEAD + dh);
                if (z == 0) {
                    uint32_t hi, lo;
                    split2h(ox, oy, hi, lo);
                    *reinterpret_cast<uint32_t*>(Qh + di) = hi;
                    *reinterpret_cast<uint32_t*>(Ql + di) = lo;
                } else if (z == 1) {
                    *reinterpret_cast<uint32_t*>(Ko + di) = pack2h(ox, oy);
                } else {
                    *reinterpret_cast<uint32_t*>(Vo + di) = pack2h(ox, oy);
                }
            }
        }
    }
}

// Output projection: 512 threads, fp32 row-major C.
__global__ __launch_bounds__(512, 1)
void gemm_out16(const __half* __restrict__ Ah, const __half* __restrict__ Al,
                const __half* __restrict__ W,
                const float* __restrict__ bias, float* __restrict__ C)
{
    extern __shared__ char smem[];
    const uint32_t sbase = smem_u32(smem);
    const int tid = threadIdx.x;

    const int m0 = blockIdx.y * 128;
    const int n0 = blockIdx.x * 128;

    float acc[2][4][4];
#pragma unroll
    for (int i = 0; i < 2; i++)
#pragma unroll
        for (int j = 0; j < 4; j++)
#pragma unroll
            for (int e = 0; e < 4; e++) acc[i][j][e] = 0.f;

    g16_core(sbase, Ah, Al, W, m0, n0, tid, acc);

    const int wid = tid >> 5;
    const int lid = tid & 31;
    const int wr = wid >> 2;
    const int wc = wid & 3;
    const int tq = lid >> 2;
    const int tr = (lid & 3) * 2;
#pragma unroll
    for (int mi = 0; mi < 2; mi++) {
#pragma unroll
        for (int ni = 0; ni < 4; ni++) {
            int gm = m0 + wr * 32 + mi * 16 + tq;
            int gn = n0 + wc * 32 + ni * 8 + tr;
            float2 bb = *reinterpret_cast<const float2*>(bias + gn);
#pragma unroll
            for (int half = 0; half < 2; half++) {
                int row = gm + half * 8;
                float2 o;
                o.x = acc[mi][ni][half * 2 + 0] + bb.x;
                o.y = acc[mi][ni][half * 2 + 1] + bb.y;
                *reinterpret_cast<float2*>(C + (size_t)row * DMODEL + gn) = o;
            }
        }
    }
}

// ---------------------------------------------------------------------------
// fp16 causal flash attention. 256 threads (8 warps), 128 queries per CTA,
// key tiles of 64, cp.async 2-stage, 1 barrier/iter, deferred l-reduction.
// ---------------------------------------------------------------------------
#define KST    72
#define A_ARR  9216                  // 64*KST*2
#define A_STG  (2 * A_ARR)           // K + V per stage
#define A_SMEM (2 * A_STG)           // 36864

__device__ __forceinline__ void attn_issue(
    uint32_t sbase, int st,
    const __half* kh, const __half* vh, size_t koff, int tid)
{
    uint32_t b = sbase + st * A_STG;
#pragma unroll
    for (int i = tid; i < 512; i += 256) {
        int row = i >> 3, c8 = (i & 7) * 8;
        uint32_t so = (uint32_t)(row * KST + c8) * 2;
        size_t go = koff + row * 64 + c8;
        cp16(b + so,         kh + go);
        cp16(b + A_ARR + so, vh + go);
    }
}

__global__ __launch_bounds__(256, 2) void attn_mma(
    const __half* __restrict__ qh, const __half* __restrict__ ql,
    const __half* __restrict__ kh, const __half* __restrict__ vh,
    __half* __restrict__ ch, __half* __restrict__ cl)
{
    extern __shared__ char smem[];
    const uint32_t sbase = smem_u32(smem);

    const int qt  = (int)(gridDim.x - 1) - (int)blockIdx.x;  // long blocks first
    const int bh  = blockIdx.y;
    const int tid = threadIdx.x;
    const int wq  = tid >> 5;        // 0..7 : 16-query strip
    const int lid = tid & 31;

    const size_t headoff = (size_t)bh * SEQL * DHEAD;

    // ---- stage Q hi (bytes 0..18432) / Q lo (18432..36864), load fragments
    {
        const __half* Qh = qh + headoff + (size_t)qt * 128 * DHEAD;
        const __half* Ql = ql + headoff + (size_t)qt * 128 * DHEAD;
#pragma unroll
        for (int i = tid; i < 1024; i += 256) {
            int row = i >> 3, c8 = (i & 7) * 8;
            uint32_t so = (uint32_t)(row * KST + c8) * 2;
            *reinterpret_cast<uint4*>(smem + so) =
                *reinterpret_cast<const uint4*>(Qh + row * 64 + c8);
            *reinterpret_cast<uint4*>(smem + 2 * A_ARR + so) =
                *reinterpret_cast<const uint4*>(Ql + row * 64 + c8);
        }
    }
    __syncthreads();

    const int aRow = lid & 15;
    const int aCol = (lid >> 4) << 3;
    uint32_t qfh[4][4], qfl[4][4];
#pragma unroll
    for (int ks = 0; ks < 4; ks++) {
        uint32_t off = (uint32_t)((wq * 16 + aRow) * KST + ks * 16 + aCol) * 2;
        ldm_x4(qfh[ks], sbase + off);
        ldm_x4(qfl[ks], sbase + 2 * A_ARR + off);
    }
    __syncthreads();   // Q fragments read before stage buffers are overwritten

    attn_issue(sbase, 0, kh, vh, headoff, tid);
    cp_commit();

    float O[8][4];
#pragma unroll
    for (int i = 0; i < 8; i++)
#pragma unroll
        for (int e = 0; e < 4; e++) O[i][e] = 0.f;
    float m0 = -1e30f, m1 = -1e30f, lp0 = 0.f, lp1 = 0.f;

    const int bRow = (lid & 7) + ((lid & 16) >> 1);
    const int bCol = ((lid >> 3) & 1) << 3;
    const int rg0 = qt * 128 + wq * 16 + (lid >> 2);   // global query row (+8)

    const int nkt = 2 * qt + 2;
    for (int kt = 0; kt < nkt; kt++) {
        cp_wait<0>();
        __syncthreads();
        if (kt + 1 < nkt) {
            attn_issue(sbase, (kt + 1) & 1, kh, vh,
                       headoff + (size_t)(kt + 1) * 64 * DHEAD, tid);
            cp_commit();
        }

        const uint32_t bK = sbase + (kt & 1) * A_STG;
        const uint32_t bV = bK + A_ARR;

        float S[8][4];
#pragma unroll
        for (int i = 0; i < 8; i++)
#pragma unroll
            for (int e = 0; e < 4; e++) S[i][e] = 0.f;
#pragma unroll
        for (int ks = 0; ks < 4; ks++) {
#pragma unroll
            for (int ng = 0; ng < 4; ng++) {
                uint32_t kf[4];
                uint32_t off = (uint32_t)((ng * 16 + bRow) * KST + ks * 16 + bCol) * 2;
                ldm_x4(kf, bK + off);
#pragma unroll
                for (int s = 0; s < 2; s++) {
                    float* d = S[ng * 2 + s];
                    mma_f16(d, qfh[ks], kf[s * 2], kf[s * 2 + 1]);
                    mma_f16(d, qfl[ks], kf[s * 2], kf[s * 2 + 1]);
                }
            }
        }

        // causal mask: only the (at most two) diagonal key tiles need it
        if (kt >= 2 * qt) {
            int cg = kt * 64 + (lid & 3) * 2;
#pragma unroll
            for (int ni = 0; ni < 8; ni++) {
                int c = cg + ni * 8;
                if (c > rg0)         S[ni][0] = -1e30f;
                if (c + 1 > rg0)     S[ni][1] = -1e30f;
                if (c > rg0 + 8)     S[ni][2] = -1e30f;
                if (c + 1 > rg0 + 8) S[ni][3] = -1e30f;
            }
        }

        float mx0 = -1e30f, mx1 = -1e30f;
#pragma unroll
        for (int ni = 0; ni < 8; ni++) {
            mx0 = fmaxf(mx0, fmaxf(S[ni][0], S[ni][1]));
            mx1 = fmaxf(mx1, fmaxf(S[ni][2], S[ni][3]));
        }
        mx0 = fmaxf(mx0, __shfl_xor_sync(0xffffffffu, mx0, 1));
        mx0 = fmaxf(mx0, __shfl_xor_sync(0xffffffffu, mx0, 2));
        mx1 = fmaxf(mx1, __shfl_xor_sync(0xffffffffu, mx1, 1));
        mx1 = fmaxf(mx1, __shfl_xor_sync(0xffffffffu, mx1, 2));
        float mn0 = fmaxf(m0, mx0), mn1 = fmaxf(m1, mx1);
        float c0 = __expf(m0 - mn0), c1 = __expf(m1 - mn1);
        m0 = mn0; m1 = mn1;

        uint32_t pA[8], pB[8];
        float s0 = 0.f, s1 = 0.f;
#pragma unroll
        for (int ni = 0; ni < 8; ni++) {
            float p0 = __expf(S[ni][0] - m0);
            float p1 = __expf(S[ni][1] - m0);
            float p2 = __expf(S[ni][2] - m1);
            float p3 = __expf(S[ni][3] - m1);
            s0 += p0 + p1;
            s1 += p2 + p3;
            pA[ni] = pack2h(p0, p1);
            pB[ni] = pack2h(p2, p3);
        }
        lp0 = lp0 * c0 + s0;       // deferred cross-lane reduction
        lp1 = lp1 * c1 + s1;
#pragma unroll
        for (int ni = 0; ni < 8; ni++) {
            O[ni][0] *= c0; O[ni][1] *= c0;
            O[ni][2] *= c1; O[ni][3] *= c1;
        }

#pragma unroll
        for (int ks = 0; ks < 4; ks++) {
            uint32_t aP[4] = {pA[2 * ks], pB[2 * ks], pA[2 * ks + 1], pB[2 * ks + 1]};
#pragma unroll
            for (int ng = 0; ng < 4; ng++) {
                uint32_t vf[4];
                uint32_t off = (uint32_t)((ks * 16 + (lid & 15)) * KST + ng * 16 + ((lid >> 4) << 3)) * 2;
                ldm_x4_t(vf, bV + off);
#pragma unroll
                for (int s = 0; s < 2; s++)
                    mma_f16(O[ng * 2 + s], aP, vf[s * 2], vf[s * 2 + 1]);
            }
        }
    }

    // ---- final l reduction (once), normalize, split fp16 hi/lo, scatter
    float l0 = lp0 + __shfl_xor_sync(0xffffffffu, lp0, 1);
    l0 += __shfl_xor_sync(0xffffffffu, l0, 2);
    float l1 = lp1 + __shfl_xor_sync(0xffffffffu, lp1, 1);
    l1 += __shfl_xor_sync(0xffffffffu, l1, 2);
    const float inv0 = 1.f / l0;
    const float inv1 = 1.f / l1;
    const int b = bh >> 4;
    const int h = bh & 15;
    const int sq = qt * 128 + wq * 16 + (lid >> 2);
#pragma unroll
    for (int ni = 0; ni < 8; ni++) {
        int col = h * 64 + ni * 8 + (lid & 3) * 2;
        uint32_t hi, lo;
        split2h(O[ni][0] * inv0, O[ni][1] * inv0, hi, lo);
        size_t d0 = (size_t)(sq * BATCH + b) * DMODEL + col;
        *reinterpret_cast<uint32_t*>(ch + d0) = hi;
        *reinterpret_cast<uint32_t*>(cl + d0) = lo;
        split2h(O[ni][2] * inv1, O[ni][3] * inv1, hi, lo);
        size_t d1 = (size_t)((sq + 8) * BATCH + b) * DMODEL + col;
        *reinterpret_cast<uint32_t*>(ch + d1) = hi;
        *reinterpret_cast<uint32_t*>(cl + d1) = lo;
    }
}

// ---------------------------------------------------------------------------
// Launch
// ---------------------------------------------------------------------------
extern "C" void kernel_launch(void* const* d_in, const int* in_sizes, int n_in,
                              void* d_out, int out_size)
{
    const float* query = (const float*)d_in[0];
    const float* q_w   = (const float*)d_in[1];
    const float* q_b   = (const float*)d_in[2];
    const float* k_w   = (const float*)d_in[3];
    const float* k_b   = (const float*)d_in[4];
    const float* v_w   = (const float*)d_in[5];
    const float* v_b   = (const float*)d_in[6];
    const float* out_w = (const float*)d_in[7];
    const float* out_b = (const float*)d_in[8];
    float* out = (float*)d_out;

    __half *x16h, *x16l, *c16h, *c16l;
    __half *qw16, *kw16, *vw16, *ow16, *qhp, *qlp, *khp, *vhp;
    cudaGetSymbolAddress((void**)&x16h, g_x16h);
    cudaGetSymbolAddress((void**)&x16l, g_x16l);
    cudaGetSymbolAddress((void**)&c16h, g_c16h);
    cudaGetSymbolAddress((void**)&c16l, g_c16l);
    cudaGetSymbolAddress((void**)&qw16, g_qw16);
    cudaGetSymbolAddress((void**)&kw16, g_kw16);
    cudaGetSymbolAddress((void**)&vw16, g_vw16);
    cudaGetSymbolAddress((void**)&ow16, g_ow16);
    cudaGetSymbolAddress((void**)&qhp, g_qh);
    cudaGetSymbolAddress((void**)&qlp, g_ql);
    cudaGetSymbolAddress((void**)&khp, g_kh);
    cudaGetSymbolAddress((void**)&vhp, g_vh);

    static bool attr_done = false;
    if (!attr_done) {
        cudaFuncSetAttribute(gemm_qkv16, cudaFuncAttributeMaxDynamicSharedMemorySize, Q_SMEM);
        cudaFuncSetAttribute(gemm_out16, cudaFuncAttributeMaxDynamicSharedMemorySize, Q_SMEM);
        cudaFuncSetAttribute(attn_mma,   cudaFuncAttributeMaxDynamicSharedMemorySize, A_SMEM);
        attr_done = true;
    }

    const int nTok = MTOK * DMODEL;      // 4M
    const int nW   = DMODEL * DMODEL;    // 1M

    cvt_x16<<<nTok / 1024, 256>>>(query, x16h, x16l, nTok);
    dim3 gw(nW / 1024, 4);
    cvt_w4_16<<<gw, 256>>>(q_w, k_w, v_w, out_w, qw16, kw16, vw16, ow16, nW);

    dim3 gqkv(DMODEL / 128, MTOK / 128, 3);   // (8, 32, 3)
    gemm_qkv16<<<gqkv, 512, Q_SMEM>>>(x16h, x16l, qw16, kw16, vw16,
                                      q_b, k_b, v_b, qhp, qlp, khp, vhp);

    dim3 gattn(SEQL / 128, NBH);              // (16, 32)
    attn_mma<<<gattn, 256, A_SMEM>>>(qhp, qlp, khp, vhp, c16h, c16l);

    dim3 gout(DMODEL / 128, MTOK / 128);      // (8, 32)
    gemm_out16<<<gout, 512, Q_SMEM>>>(c16h, c16l, ow16, out_b, out);
}